// round 12
// baseline (speedup 1.0000x reference)
#include <cuda_runtime.h>
#include <math.h>
#include <stdint.h>

#define LSEQ  2048
#define NB    2
#define DM    768
#define DIN   1536
#define NH    24
#define HD    64
#define DS    16
#define CONVD 1568
#define DPROJ 3128

#define NCH 16
#define CT  (LSEQ/NCH)

#define TM 128
#define TN 128
#define GK 32
#define ASTRIDE 36
#define ABYTES (128*ASTRIDE*4)          // 18432
#define BBYTES (128*32*4)               // 16384
#define STAGEB (ABYTES+BBYTES)          // 34816
#define NSTAGE 3
#define DSMEM  (NSTAGE*STAGEB)          // 104448

// ---------------- scratch (device globals) ----------------------------------
__device__ float g_zx[2][NB][LSEQ][DPROJ];
__device__ float g_xc[2][NB][LSEQ][CONVD];
__device__ float g_dt[2][NB][LSEQ][NH];
__device__ float g_dA[2][NB][LSEQ][NH];
__device__ float g_y [2][NB][LSEQ][DIN];
__device__ float g_hend[2][NB][NH][NCH][HD][DS];
__device__ float g_hin [2][NB][NH][NCH][HD][DS];
__device__ float g_cpe [2][NB][NH][NCH];
// tf32-pre-rounded GEMM operands. A-side (xr, pwr, y): plain k order.
// B-side (iwr, owT, M): k-permuted within 16-blocks.
__device__ float g_xr [NB*LSEQ*DM];
__device__ float g_iwr[2][DPROJ*DM];
__device__ float g_pwr[DM*2*DM];
__device__ float g_owT[2][DIN*DM];
__device__ float g_M  [2][DM*DIN];

// ---------------- helpers ----------------------------------------------------
__device__ __forceinline__ uint32_t s2u(const void* p){
    uint32_t a;
    asm("{ .reg .u64 t; cvta.to.shared.u64 t, %1; cvt.u32.u64 %0, t; }" : "=r"(a) : "l"(p));
    return a;
}
__device__ __forceinline__ float rna_tf32(float f){
    uint32_t t; asm("cvt.rna.tf32.f32 %0, %1;" : "=r"(t) : "f"(f));
    return __uint_as_float(t);
}
// k-permutation within 16-blocks: logical k -> physical 4*(k%4)+k/4
__device__ __forceinline__ int kperm(int k){
    return (k & ~15) | ((k & 3) << 2) | ((k >> 2) & 3);
}
__device__ __forceinline__ void cpa16(uint32_t dst, const float* src, bool p){
    int sz = p ? 16 : 0;
    asm volatile("cp.async.cg.shared.global [%0], [%1], 16, %2;"
                 :: "r"(dst), "l"(src), "r"(sz) : "memory");
}
#define CP_COMMIT() asm volatile("cp.async.commit_group;" ::: "memory")
#define CP_WAIT1()  asm volatile("cp.async.wait_group 1;" ::: "memory")
__device__ __forceinline__ void mma_tf32(float* d,
                                         float a0, float a1, float a2, float a3,
                                         float b0, float b1){
    asm volatile("mma.sync.aligned.m16n8k8.row.col.f32.tf32.tf32.f32 "
                 "{%0,%1,%2,%3}, {%4,%5,%6,%7}, {%8,%9}, {%0,%1,%2,%3};"
                 : "+f"(d[0]), "+f"(d[1]), "+f"(d[2]), "+f"(d[3])
                 : "r"(__float_as_uint(a0)), "r"(__float_as_uint(a1)),
                   "r"(__float_as_uint(a2)), "r"(__float_as_uint(a3)),
                   "r"(__float_as_uint(b0)), "r"(__float_as_uint(b1)));
}

// ---------------- tf32 mma.sync GEMM core ------------------------------------
// 256 threads, warp tile 32x64 (4 m-warps x 2 n-warps), CTA 128x128,
// cp.async 3-stage. A: padded-36 smem, plain k, LDS.32 feeds.
// B: 128B-row smem, k-permuted global (kperm), parity-swizzled LDS.128 feeds.
// acc[m,n] = sum_k A0[m,k]*B0[n,k] (+ A1*B1 if K1>0)
__device__ __forceinline__ void gemm_tc(
    const float* __restrict__ A0, long lda0, const float* __restrict__ B0, int ldb0, int K0,
    const float* __restrict__ A1, long lda1, const float* __restrict__ B1, int ldb1, int K1,
    int nvalid, float* __restrict__ Cbase, long crs,
    const float* __restrict__ bias, bool round_out, bool permute_cols)
{
    extern __shared__ float dsm[];
    const uint32_t smBase = s2u(dsm);
    const int tid  = threadIdx.x;
    const int lane = tid & 31;
    const int wid  = tid >> 5;
    const int wm   = wid & 3;           // 4 m-warps * 32 rows
    const int wn   = wid >> 2;          // 2 n-warps * 64 cols
    const int g    = lane >> 2;
    const int tg   = lane & 3;
    const int gpar = (g & 1) << 2;      // B-read parity swizzle

    float acc[2][8][4];
#pragma unroll
    for (int mt = 0; mt < 2; mt++)
#pragma unroll
        for (int nt = 0; nt < 8; nt++)
#pragma unroll
            for (int q = 0; q < 4; q++) acc[mt][nt][q] = 0.f;

    const int NC0 = K0 / GK;
    const int NC  = NC0 + K1 / GK;

    auto load = [&](int chunk, int s){
        const float* Ab; long la; const float* Bb; int lb; int kt;
        if (chunk < NC0) { Ab = A0; la = lda0; Bb = B0; lb = ldb0; kt = chunk*GK; }
        else             { Ab = A1; la = lda1; Bb = B1; lb = ldb1; kt = (chunk-NC0)*GK; }
        int row = tid >> 1;             // 128 rows, 2 threads per row
        int u0  = (tid & 1) * 4;        // 4 float4 units each
        uint32_t stA = smBase + s*STAGEB;
        uint32_t adst = stA + (uint32_t)(row*ASTRIDE + u0*4)*4;
        uint32_t bbase = stA + ABYTES + (uint32_t)row*128;
        uint32_t sw = (uint32_t)((row & 1) << 2);
        const float* arow = Ab + (long)row*la + kt + u0*4;
        const float* brow = Bb + (long)row*lb + kt + u0*4;
        bool bp = row < nvalid;
#pragma unroll
        for (int u = 0; u < 4; u++) {
            cpa16(adst + u*16, arow + u*4, true);
            cpa16(bbase + (uint32_t)(((u0 + u) ^ sw) << 4), brow + u*4, bp);
        }
    };
    auto compute = [&](int s){
        const float* As_ = dsm + s*(STAGEB/4);
        const float* Bs_ = As_ + ABYTES/4;
#pragma unroll
        for (int half = 0; half < 2; half++) {
            int su = ((half*4 + tg) ^ gpar) * 4;
            float4 bv[8];
#pragma unroll
            for (int nt = 0; nt < 8; nt++) {
                int rb = wn*64 + nt*8 + g;
                bv[nt] = *(const float4*)(Bs_ + rb*32 + su);
            }
#pragma unroll
            for (int step = 0; step < 2; step++) {
                int kk = half*16 + step*8;
                float af[2][4];
#pragma unroll
                for (int mt = 0; mt < 2; mt++) {
                    const float* ap = As_ + (wm*32 + mt*16 + g)*ASTRIDE + kk + tg;
                    af[mt][0] = ap[0];
                    af[mt][1] = ap[8*ASTRIDE];
                    af[mt][2] = ap[4];
                    af[mt][3] = ap[8*ASTRIDE + 4];
                }
                if (step == 0) {
#pragma unroll
                    for (int mt = 0; mt < 2; mt++)
#pragma unroll
                        for (int nt = 0; nt < 8; nt++)
                            mma_tf32(acc[mt][nt], af[mt][0], af[mt][1], af[mt][2], af[mt][3],
                                     bv[nt].x, bv[nt].y);
                } else {
#pragma unroll
                    for (int mt = 0; mt < 2; mt++)
#pragma unroll
                        for (int nt = 0; nt < 8; nt++)
                            mma_tf32(acc[mt][nt], af[mt][0], af[mt][1], af[mt][2], af[mt][3],
                                     bv[nt].z, bv[nt].w);
                }
            }
        }
    };

    load(0, 0); CP_COMMIT();
    load(1, 1); CP_COMMIT();

    for (int i = 0; i < NC; i++) {
        CP_WAIT1();
        __syncthreads();
        if (i + 2 < NC) load(i + 2, (i + 2) % NSTAGE);
        CP_COMMIT();
        compute(i % NSTAGE);
    }

#pragma unroll
    for (int mt = 0; mt < 2; mt++) {
        int r0 = wm*32 + mt*16 + g;
#pragma unroll
        for (int nt = 0; nt < 8; nt++) {
            int col = wn*64 + nt*8 + 2*tg;
            float d0 = acc[mt][nt][0], d1 = acc[mt][nt][1];
            float d2 = acc[mt][nt][2], d3 = acc[mt][nt][3];
            if (bias) { d0 += bias[col]; d1 += bias[col+1]; d2 += bias[col]; d3 += bias[col+1]; }
            if (round_out) {
                d0 = rna_tf32(d0); d1 = rna_tf32(d1);
                d2 = rna_tf32(d2); d3 = rna_tf32(d3);
            }
            if (permute_cols) {
                int c0 = kperm(col), c1 = kperm(col+1);
                Cbase[(long)r0*crs + c0]     = d0;
                Cbase[(long)r0*crs + c1]     = d1;
                Cbase[(long)(r0+8)*crs + c0] = d2;
                Cbase[(long)(r0+8)*crs + c1] = d3;
            } else if (col + 1 < nvalid) {
                *reinterpret_cast<float2*>(Cbase + (long)r0*crs + col)     = make_float2(d0, d1);
                *reinterpret_cast<float2*>(Cbase + (long)(r0+8)*crs + col) = make_float2(d2, d3);
            } else if (col < nvalid) {
                Cbase[(long)r0*crs + col]     = d0;
                Cbase[(long)(r0+8)*crs + col] = d2;
            }
        }
    }
}

// ---------------- GEMM wrappers ---------------------------------------------
__global__ __launch_bounds__(256, 2) void k_in_proj()
{
    int dir = blockIdx.z, m0 = blockIdx.y*TM, n0 = blockIdx.x*TN;
    int b = m0 >> 11, l0 = m0 & 2047;
    const float* Abase; long ars;
    if (dir == 0) { Abase = g_xr + (size_t)m0*DM;                     ars =  DM; }
    else          { Abase = g_xr + ((size_t)b*LSEQ + (LSEQ-1-l0))*DM; ars = -(long)DM; }
    int nvalid = DPROJ - n0; if (nvalid > TN) nvalid = TN;
    gemm_tc(Abase, ars, &g_iwr[dir][0] + (size_t)n0*DM, DM, DM,
            nullptr, 0, nullptr, 0, 0,
            nvalid, &g_zx[dir][0][0][0] + (size_t)m0*DPROJ + n0, DPROJ,
            nullptr, false, false);
}

// M[dir][m, n] = sum_j pw[m, j + dir*768] * ow[j, n] ; stored k-permuted over n
__global__ __launch_bounds__(256, 2) void k_mw()
{
    int dir = blockIdx.z, m0 = blockIdx.y*TM, n0 = blockIdx.x*TN;
    gemm_tc(g_pwr + (size_t)m0*(2*DM) + dir*DM, 2*DM,
            &g_owT[dir][0] + (size_t)n0*DM, DM, DM,
            nullptr, 0, nullptr, 0, 0,
            TN, &g_M[dir][0] + (size_t)m0*DIN + n0, DIN,
            nullptr, true, true);
}

// out[m, n] = sum_k y_f[m,k] Mf[n,k] + sum_k y_b[flip(m),k] Mb[n,k] + pb[n]
__global__ __launch_bounds__(256, 2) void k_outf(const float* __restrict__ pb,
                                                 float* __restrict__ out)
{
    int m0 = blockIdx.y*TM, n0 = blockIdx.x*TN;
    int b = m0 >> 11, l0 = m0 & 2047;
    gemm_tc(&g_y[0][0][0][0] + (size_t)m0*DIN, DIN,
            &g_M[0][0] + (size_t)n0*DIN, DIN, DIN,
            &g_y[1][0][0][0] + ((size_t)b*LSEQ + (LSEQ-1-l0))*DIN, -(long)DIN,
            &g_M[1][0] + (size_t)n0*DIN, DIN, DIN,
            TN, out + (size_t)m0*DM + n0, DM, pb + n0, false, false);
}

// ---------------- fused tf32 rounding pass (kperm only on B-side iwr) --------
#define NX  (NB*LSEQ*DM)
#define NIW (DPROJ*DM)
#define NPW (DM*2*DM)
__global__ void k_round_all(const float* __restrict__ x,
                            const float* __restrict__ fiw, const float* __restrict__ biw,
                            const float* __restrict__ pw,
                            float* __restrict__ xr, float* __restrict__ iwr,
                            float* __restrict__ pwr)
{
    long i = (long)blockIdx.x * 256 + threadIdx.x;
    if (i < NX)  { xr[i] = rna_tf32(x[i]); return; }
    i -= NX;
    if (i < NIW) {
        long row = i / DM; int k = (int)(i % DM);
        iwr[row*DM + kperm(k)] = rna_tf32(fiw[i]);
        return;
    }
    i -= NIW;
    if (i < NIW) {
        long row = i / DM; int k = (int)(i % DM);
        iwr[(long)NIW + row*DM + kperm(k)] = rna_tf32(biw[i]);
        return;
    }
    i -= NIW;
    if (i < NPW) { pwr[i] = rna_tf32(pw[i]); }
}

// ---------------- transpose + round + permute out_w: (768,1536)->(1536,768) --
__global__ __launch_bounds__(256) void k_transT(const float* __restrict__ fow,
                                                const float* __restrict__ bow)
{
    __shared__ float tile[32][33];
    int dir = blockIdx.z;
    const float* src = dir ? bow : fow;
    int n0 = blockIdx.x * 32;       // over DIN
    int j0 = blockIdx.y * 32;       // over DM (k-axis of k_mw, B-side -> kperm)
    int tx = threadIdx.x & 31, ty = threadIdx.x >> 5;
#pragma unroll
    for (int q = 0; q < 4; q++)
        tile[ty + q*8][tx] = src[(size_t)(j0 + ty + q*8)*DIN + n0 + tx];
    __syncthreads();
#pragma unroll
    for (int q = 0; q < 4; q++)
        g_owT[dir][(size_t)(n0 + ty + q*8)*DM + kperm(j0 + tx)] = rna_tf32(tile[tx][ty + q*8]);
}

// ---------------- exact fp32 dt path ----------------------------------------
__global__ __launch_bounds__(256) void k_dtx(const float* __restrict__ x,
        const float* __restrict__ fw, const float* __restrict__ bw,
        const float* __restrict__ fdb, const float* __restrict__ fA,
        const float* __restrict__ bdb, const float* __restrict__ bA)
{
    __shared__ float sx[8][DM];
    int t = threadIdx.x, lane = t & 31, w = t >> 5;
    long gr0 = (long)blockIdx.x * 8;
    for (int i = t; i < 8*(DM/4); i += 256) {
        int r = i / (DM/4), c4 = i % (DM/4);
        long gr = gr0 + r;
        int l = gr & 2047; long rr = gr >> 11; int b = (int)(rr & 1), dir = (int)(rr >> 1);
        long srow = (long)b*LSEQ + (dir ? (LSEQ-1-l) : l);
        *(float4*)&sx[r][c4*4] = *(const float4*)(x + srow*DM + c4*4);
    }
    __syncthreads();
    long gr = gr0 + w;
    int l = gr & 2047; long rr = gr >> 11; int b = (int)(rr & 1), dir = (int)(rr >> 1);
    const float* W  = dir ? bw  : fw;
    const float* db = dir ? bdb : fdb;
    const float* Al = dir ? bA  : fA;
    for (int h = 0; h < NH; h++) {
        const float* wr = W + (size_t)(DIN + CONVD + h)*DM;
        float s = 0.f;
        for (int k = lane*4; k < DM; k += 128) {
            float4 a = *(const float4*)&sx[w][k];
            float4 ww = *(const float4*)(wr + k);
            s += a.x*ww.x + a.y*ww.y + a.z*ww.z + a.w*ww.w;
        }
#pragma unroll
        for (int o = 16; o; o >>= 1) s += __shfl_xor_sync(0xffffffffu, s, o);
        if (lane == 0) {
            float raw = s + db[h];
            float dt = raw > 20.f ? raw : log1pf(expf(raw));
            g_dt[dir][b][l][h] = dt;
            g_dA[dir][b][l][h] = expf(-expf(Al[h]) * dt);
        }
    }
}

// ---------------- depthwise causal conv(4) + SiLU (4 l per thread) ----------
__global__ void k_conv(const float* __restrict__ fcw, const float* __restrict__ fcb,
                       const float* __restrict__ bcw, const float* __restrict__ bcb)
{
    long idx = (long)blockIdx.x * 256 + threadIdx.x;
    if (idx >= (long)2*NB*(LSEQ/4)*CONVD) return;
    int c = (int)(idx % CONVD);
    long r = idx / CONVD;
    int lq = (int)(r % (LSEQ/4));  r /= (LSEQ/4);
    int b = (int)(r % NB);
    int dir = (int)(r / NB);
    const float* cw = dir ? bcw : fcw;
    float w0 = cw[c*4+0], w1 = cw[c*4+1], w2 = cw[c*4+2], w3 = cw[c*4+3];
    float cb = (dir ? bcb : fcb)[c];
    int l0 = lq * 4;
    const float* col = &g_zx[dir][b][0][DIN + c];
    float v[7];
#pragma unroll
    for (int k = 0; k < 7; k++) {
        int l = l0 - 3 + k;
        v[k] = (l >= 0) ? col[(size_t)l*DPROJ] : 0.f;
    }
#pragma unroll
    for (int i = 0; i < 4; i++) {
        float s = cb + v[i]*w0 + v[i+1]*w1 + v[i+2]*w2 + v[i+3]*w3;
        g_xc[dir][b][l0 + i][c] = s / (1.f + expf(-s));
    }
}

// ---------------- chunked scan: phase A (local scans) ------------------------
__global__ __launch_bounds__(64) void k_scanA()
{
    int c = blockIdx.x, h = blockIdx.y;
    int bz = blockIdx.z; int b = bz & 1, dir = bz >> 1;
    int t = threadIdx.x;
    __shared__ float sx[32][HD];
    __shared__ __align__(16) float sB[32][DS];
    __shared__ float sdt[32], sdA[32];
    __shared__ __align__(16) float sC[32][DS];
    float hs[DS];
#pragma unroll
    for (int j = 0; j < DS; j++) hs[j] = 0.f;
    float cp = 1.f;
    int base = c * CT;

    for (int l0 = 0; l0 < CT; l0 += 32) {
#pragma unroll 4
        for (int j = 0; j < 32; j++)
            sx[j][t] = g_xc[dir][b][base + l0 + j][h*HD + t];
        for (int i = t; i < 32*DS; i += 64) {
            int s = i >> 4, j = i & 15;
            sB[s][j] = g_xc[dir][b][base + l0 + s][DIN + j];
            sC[s][j] = g_xc[dir][b][base + l0 + s][DIN + DS + j];
        }
        if (t < 32) {
            sdt[t] = g_dt[dir][b][base + l0 + t][h];
            sdA[t] = g_dA[dir][b][base + l0 + t][h];
        }
        __syncthreads();
#pragma unroll 2
        for (int s = 0; s < 32; s++) {
            float dAv = sdA[s];
            cp *= dAv;
            float xv  = sdt[s] * sx[s][t];
            float4 B0 = *(const float4*)&sB[s][0];
            float4 B1 = *(const float4*)&sB[s][4];
            float4 B2 = *(const float4*)&sB[s][8];
            float4 B3 = *(const float4*)&sB[s][12];
            float4 C0 = *(const float4*)&sC[s][0];
            float4 C1 = *(const float4*)&sC[s][4];
            float4 C2 = *(const float4*)&sC[s][8];
            float4 C3 = *(const float4*)&sC[s][12];
            float y = 0.f;
            hs[0]  = hs[0]*dAv  + xv*B0.x;  y += hs[0]*C0.x;
            hs[1]  = hs[1]*dAv  + xv*B0.y;  y += hs[1]*C0.y;
            hs[2]  = hs[2]*dAv  + xv*B0.z;  y += hs[2]*C0.z;
            hs[3]  = hs[3]*dAv  + xv*B0.w;  y += hs[3]*C0.w;
            hs[4]  = hs[4]*dAv  + xv*B1.x;  y += hs[4]*C1.x;
            hs[5]  = hs[5]*dAv  + xv*B1.y;  y += hs[5]*C1.y;
            hs[6]  = hs[6]*dAv  + xv*B1.z;  y += hs[6]*C1.z;
            hs[7]  = hs[7]*dAv  + xv*B1.w;  y += hs[7]*C1.w;
            hs[8]  = hs[8]*dAv  + xv*B2.x;  y += hs[8]*C2.x;
            hs[9]  = hs[9]*dAv  + xv*B2.y;  y += hs[9]*C2.y;
            hs[10] = hs[10]*dAv + xv*B2.z;  y += hs[10]*C2.z;
            hs[11] = hs[11]*dAv + xv*B2.w;  y += hs[11]*C2.w;
            hs[12] = hs[12]*dAv + xv*B3.x;  y += hs[12]*C3.x;
            hs[13] = hs[13]*dAv + xv*B3.y;  y += hs[13]*C3.y;
            hs[14] = hs[14]*dAv + xv*B3.z;  y += hs[14]*C3.z;
            hs[15] = hs[15]*dAv + xv*B3.w;  y += hs[15]*C3.w;
            g_y[dir][b][base + l0 + s][h*HD + t] = y;
        }
        __syncthreads();
    }
    float4* he = (float4*)&g_hend[dir][b][h][c][t][0];
    he[0] = make_float4(hs[0], hs[1], hs[2], hs[3]);
    he[1] = make_float4(hs[4], hs[5], hs[6], hs[7]);
    he[2] = make_float4(hs[8], hs[9], hs[10], hs[11]);
    he[3] = make_float4(hs[12], hs[13], hs[14], hs[15]);
    if (t == 0) g_cpe[dir][b][h][c] = cp;
}

// ---------------- chunked scan: phase B (chunk prefix) -----------------------
__global__ __launch_bounds__(64) void k_scanB()
{
    int h = blockIdx.x, b = blockIdx.y, dir = blockIdx.z;
    int t = threadIdx.x;
    float hin[DS];
#pragma unroll
    for (int j = 0; j < DS; j++) hin[j] = 0.f;
    for (int c = 0; c < NCH; c++) {
        float4* hp = (float4*)&g_hin[dir][b][h][c][t][0];
        hp[0] = make_float4(hin[0], hin[1], hin[2], hin[3]);
        hp[1] = make_float4(hin[4], hin[5], hin[6], hin[7]);
        hp[2] = make_float4(hin[8], hin[9], hin[10], hin[11]);
        hp[3] = make_float4(hin[12], hin[13], hin[14], hin[15]);
        float cpe = g_cpe[dir][b][h][c];
        const float4* he = (const float4*)&g_hend[dir][b][h][c][t][0];
        float4 e0 = he[0], e1 = he[1], e2 = he[2], e3 = he[3];
        hin[0]  = hin[0]*cpe  + e0.x;  hin[1]  = hin[1]*cpe  + e0.y;
        hin[2]  = hin[2]*cpe  + e0.z;  hin[3]  = hin[3]*cpe  + e0.w;
        hin[4]  = hin[4]*cpe  + e1.x;  hin[5]  = hin[5]*cpe  + e1.y;
        hin[6]  = hin[6]*cpe  + e1.z;  hin[7]  = hin[7]*cpe  + e1.w;
        hin[8]  = hin[8]*cpe  + e2.x;  hin[9]  = hin[9]*cpe  + e2.y;
        hin[10] = hin[10]*cpe + e2.z;  hin[11] = hin[11]*cpe + e2.w;
        hin[12] = hin[12]*cpe + e3.x;  hin[13] = hin[13]*cpe + e3.y;
        hin[14] = hin[14]*cpe + e3.z;  hin[15] = hin[15]*cpe + e3.w;
    }
}

// ---------------- chunked scan: phase C (carry-in correction) ----------------
__global__ __launch_bounds__(64) void k_scanC()
{
    int c = blockIdx.x + 1;
    int h = blockIdx.y;
    int bz = blockIdx.z; int b = bz & 1, dir = bz >> 1;
    int t = threadIdx.x;
    __shared__ __align__(16) float sC[32][DS];
    __shared__ float sdA[32];
    float hin[DS];
    {
        const float4* hp = (const float4*)&g_hin[dir][b][h][c][t][0];
        float4 a0 = hp[0], a1 = hp[1], a2 = hp[2], a3 = hp[3];
        hin[0]=a0.x; hin[1]=a0.y; hin[2]=a0.z; hin[3]=a0.w;
        hin[4]=a1.x; hin[5]=a1.y; hin[6]=a1.z; hin[7]=a1.w;
        hin[8]=a2.x; hin[9]=a2.y; hin[10]=a2.z; hin[11]=a2.w;
        hin[12]=a3.x; hin[13]=a3.y; hin[14]=a3.z; hin[15]=a3.w;
    }
    float cp = 1.f;
    int base = c * CT;
    for (int l0 = 0; l0 < CT; l0 += 32) {
        for (int i = t; i < 32*DS; i += 64) {
            int s = i >> 4, j = i & 15;
            sC[s][j] = g_xc[dir][b][base + l0 + s][DIN + DS + j];
        }
        if (t < 32) sdA[t] = g_dA[dir][b][base + l0 + t][h];
        __syncthreads();
#pragma unroll 4
        for (int s = 0; s < 32; s++) {
            cp *= sdA[s];
            float4 C0 = *(const float4*)&sC[s][0];
            float4 C1 = *(const float4*)&sC[s][4];
            float4 C2 = *(const float4*)&sC[s][8];
            float4 C3 = *(const float4*)&sC[s][12];
            float d = hin[0]*C0.x + hin[1]*C0.y + hin[2]*C0.z + hin[3]*C0.w
                    + hin[4]*C1.x + hin[5]*C1.y + hin[6]*C1.z + hin[7]*C1.w
                    + hin[8]*C2.x + hin[9]*C2.y + hin[10]*C2.z + hin[11]*C2.w
                    + hin[12]*C3.x + hin[13]*C3.y + hin[14]*C3.z + hin[15]*C3.w;
            g_y[dir][b][base + l0 + s][h*HD + t] += cp * d;
        }
        __syncthreads();
    }
}

// ---- y += Dp*xh; gate silu(z); RMSNorm; store tf32-rounded (plain order) ----
__global__ void k_gate_norm(const float* __restrict__ fDp, const float* __restrict__ fnw,
                            const float* __restrict__ bDp, const float* __restrict__ bnw)
{
    int row = blockIdx.x;
    int l = row % LSEQ;
    int r = row / LSEQ;
    int b = r % NB;
    int dir = r / NB;
    const float* Dp = dir ? bDp : fDp;
    const float* nw = dir ? bnw : fnw;
    float vals[6];
    float sq = 0.f;
#pragma unroll
    for (int ii = 0; ii < 6; ii++) {
        int i = threadIdx.x + ii*256;
        int hh = i >> 6;
        float xh = g_xc[dir][b][l][i];
        float yv = g_y[dir][b][l][i] + Dp[hh]*xh;
        float z  = g_zx[dir][b][l][i];
        yv *= z / (1.f + expf(-z));
        vals[ii] = yv;
        sq += yv*yv;
    }
#pragma unroll
    for (int o = 16; o; o >>= 1) sq += __shfl_xor_sync(0xffffffffu, sq, o);
    __shared__ float ssum[8];
    __shared__ float sscale;
    int w = threadIdx.x >> 5;
    if ((threadIdx.x & 31) == 0) ssum[w] = sq;
    __syncthreads();
    if (threadIdx.x == 0) {
        float tot = 0.f;
        for (int i = 0; i < 8; i++) tot += ssum[i];
        sscale = rsqrtf(tot/(float)DIN + 1e-5f);
    }
    __syncthreads();
    float scale = sscale;
#pragma unroll
    for (int ii = 0; ii < 6; ii++) {
        int i = threadIdx.x + ii*256;
        g_y[dir][b][l][i] = rna_tf32(vals[ii]*scale*nw[i]);
    }
}

// ---------------- launch -----------------------------------------------------
extern "C" void kernel_launch(void* const* d_in, const int* in_sizes, int n_in,
                              void* d_out, int out_size)
{
    const float* x      = (const float*)d_in[0];
    const float* pw     = (const float*)d_in[1];
    const float* pb     = (const float*)d_in[2];
    const float* f_in_w = (const float*)d_in[3];
    const float* f_cw   = (const float*)d_in[4];
    const float* f_cb   = (const float*)d_in[5];
    const float* f_db   = (const float*)d_in[6];
    const float* f_Al   = (const float*)d_in[7];
    const float* f_Dp   = (const float*)d_in[8];
    const float* f_nw   = (const float*)d_in[9];
    const float* f_ow   = (const float*)d_in[10];
    const float* b_in_w = (const float*)d_in[11];
    const float* b_cw   = (const float*)d_in[12];
    const float* b_cb   = (const float*)d_in[13];
    const float* b_db   = (const float*)d_in[14];
    const float* b_Al   = (const float*)d_in[15];
    const float* b_Dp   = (const float*)d_in[16];
    const float* b_nw   = (const float*)d_in[17];
    const float* b_ow   = (const float*)d_in[18];
    float* out = (float*)d_out;

    cudaFuncSetAttribute(k_in_proj, cudaFuncAttributeMaxDynamicSharedMemorySize, DSMEM);
    cudaFuncSetAttribute(k_mw,      cudaFuncAttributeMaxDynamicSharedMemorySize, DSMEM);
    cudaFuncSetAttribute(k_outf,    cudaFuncAttributeMaxDynamicSharedMemorySize, DSMEM);

    float* xr  = nullptr; cudaGetSymbolAddress((void**)&xr,  g_xr);
    float* iwr = nullptr; cudaGetSymbolAddress((void**)&iwr, g_iwr);
    float* pwr = nullptr; cudaGetSymbolAddress((void**)&pwr, g_pwr);

    dim3 blk(256);
    long ntot = (long)NX + 2*NIW + NPW;
    k_round_all<<<(unsigned)((ntot + 255)/256), blk>>>(x, f_in_w, b_in_w, pw, xr, iwr, pwr);
    k_transT<<<dim3(DIN/32, DM/32, 2), blk>>>(f_ow, b_ow);
    k_mw<<<dim3(DIN/TN, DM/TM, 2), blk, DSMEM>>>();

    k_in_proj<<<dim3((DPROJ + TN - 1)/TN, (NB*LSEQ)/TM, 2), blk, DSMEM>>>();
    k_dtx<<<2*NB*LSEQ/8, blk>>>(x, f_in_w, b_in_w, f_db, f_Al, b_db, b_Al);

    long nconv = (long)2*NB*(LSEQ/4)*CONVD;
    k_conv<<<(unsigned)((nconv + 255)/256), blk>>>(f_cw, f_cb, b_cw, b_cb);

    k_scanA<<<dim3(NCH, NH, NB*2), 64>>>();
    k_scanB<<<dim3(NH, NB, 2), 64>>>();
    k_scanC<<<dim3(NCH - 1, NH, NB*2), 64>>>();

    k_gate_norm<<<2*NB*LSEQ, blk>>>(f_Dp, f_nw, b_Dp, b_nw);

    k_outf<<<dim3(DM/TN, (NB*LSEQ)/TM, 1), blk, DSMEM>>>(pb, out);
}

// round 13
// speedup vs baseline: 1.2354x; 1.2354x over previous
#include <cuda_runtime.h>
#include <math.h>
#include <stdint.h>

#define LSEQ  2048
#define NB    2
#define DM    768
#define DIN   1536
#define NH    24
#define HD    64
#define DS    16
#define CONVD 1568
#define DPROJ 3128

#define NCH 16
#define CT  (LSEQ/NCH)

#define TM 128
#define TN 128
#define GK 32
#define SSTRIDE 36
#define STAGEF (128*SSTRIDE)            // floats per operand per stage
#define STAGEB (2*STAGEF*4)             // bytes per stage (A+B)
#define NSTAGE 3
#define DSMEM  (NSTAGE*STAGEB)          // 110592 B

// ---------------- scratch (device globals) ----------------------------------
__device__ float g_zx[2][NB][LSEQ][DPROJ];
__device__ float g_xc[2][NB][LSEQ][CONVD];
__device__ float g_dt[2][NB][LSEQ][NH];
__device__ float g_dA[2][NB][LSEQ][NH];
__device__ float g_y [2][NB][LSEQ][DIN];
__device__ float g_hend[2][NB][NH][NCH][HD][DS];
__device__ float g_hin [2][NB][NH][NCH][HD][DS];
__device__ float g_cpe [2][NB][NH][NCH];
// tf32-pre-rounded GEMM operands
__device__ float g_xr [NB*LSEQ*DM];
__device__ float g_iwr[2][DPROJ*DM];
__device__ float g_pwr[DM*2*DM];
__device__ float g_owT[2][DIN*DM];
__device__ float g_M  [2][DM*DIN];

// ---------------- helpers ----------------------------------------------------
__device__ __forceinline__ uint32_t s2u(const void* p){
    uint32_t a;
    asm("{ .reg .u64 t; cvta.to.shared.u64 t, %1; cvt.u32.u64 %0, t; }" : "=r"(a) : "l"(p));
    return a;
}
__device__ __forceinline__ float rna_tf32(float f){
    uint32_t t; asm("cvt.rna.tf32.f32 %0, %1;" : "=r"(t) : "f"(f));
    return __uint_as_float(t);
}
__device__ __forceinline__ void cpa16(uint32_t dst, const float* src, bool p){
    int sz = p ? 16 : 0;
    asm volatile("cp.async.cg.shared.global [%0], [%1], 16, %2;"
                 :: "r"(dst), "l"(src), "r"(sz) : "memory");
}
#define CP_COMMIT() asm volatile("cp.async.commit_group;" ::: "memory")
#define CP_WAIT1()  asm volatile("cp.async.wait_group 1;" ::: "memory")
__device__ __forceinline__ void mma_tf32(float& d0, float& d1, float& d2, float& d3,
                                         uint32_t a0, uint32_t a1, uint32_t a2, uint32_t a3,
                                         uint32_t b0, uint32_t b1){
    asm volatile("mma.sync.aligned.m16n8k8.row.col.f32.tf32.tf32.f32 "
                 "{%0,%1,%2,%3}, {%4,%5,%6,%7}, {%8,%9}, {%0,%1,%2,%3};"
                 : "+f"(d0), "+f"(d1), "+f"(d2), "+f"(d3)
                 : "r"(a0), "r"(a1), "r"(a2), "r"(a3), "r"(b0), "r"(b1));
}

// ---------------- tf32 mma.sync GEMM core (cp.async 3-stage, 2-pass) ---------
// Operands MUST be pre-rounded to tf32.
// acc[m,n] = sum_k A0[m,k]*B0[n,k]  (+ sum_k A1[m,k]*B1[n,k] if K1>0)
__device__ __forceinline__ void gemm_tc(
    const float* __restrict__ A0, long lda0, const float* __restrict__ B0, int ldb0, int K0,
    const float* __restrict__ A1, long lda1, const float* __restrict__ B1, int ldb1, int K1,
    int nvalid, float* __restrict__ Cbase, long crs,
    const float* __restrict__ bias, bool round_out)
{
    extern __shared__ float dsm[];
    const uint32_t smBase = s2u(dsm);
    const int tid  = threadIdx.x;
    const int lane = tid & 31;
    const int wid  = tid >> 5;
    const int wm   = wid & 3;
    const int wn   = wid >> 2;
    const int g    = lane >> 2;
    const int tg   = lane & 3;
    const int lr   = tid >> 3;
    const int lc   = tid & 7;

    float acc[2][8][4];
#pragma unroll
    for (int mt = 0; mt < 2; mt++)
#pragma unroll
        for (int nt = 0; nt < 8; nt++)
#pragma unroll
            for (int q = 0; q < 4; q++) acc[mt][nt][q] = 0.f;

    const int NC0 = K0 / GK;
    const int NC  = NC0 + K1 / GK;

    auto load = [&](int chunk, int s){
        const float* Ab; long la; const float* Bb; int lb; int kt;
        if (chunk < NC0) { Ab = A0; la = lda0; Bb = B0; lb = ldb0; kt = chunk*GK; }
        else             { Ab = A1; la = lda1; Bb = B1; lb = ldb1; kt = (chunk-NC0)*GK; }
        uint32_t stA = smBase + s*STAGEB;
        uint32_t stB = stA + STAGEF*4;
#pragma unroll
        for (int j = 0; j < 4; j++) {
            int r = lr + j*32;
            cpa16(stA + (uint32_t)(r*SSTRIDE + lc*4)*4, Ab + (long)r*la + kt + lc*4, true);
            cpa16(stB + (uint32_t)(r*SSTRIDE + lc*4)*4, Bb + (long)r*lb + kt + lc*4, r < nvalid);
        }
    };
    auto compute = [&](int s){
        const float* As_ = dsm + s*(2*STAGEF);
        const float* Bs_ = As_ + STAGEF;
#pragma unroll
        for (int kk = 0; kk < GK; kk += 8) {
            uint32_t af[2][4];
#pragma unroll
            for (int mt = 0; mt < 2; mt++) {
                const uint32_t* ap = reinterpret_cast<const uint32_t*>(
                    As_ + (wm*32 + mt*16 + g)*SSTRIDE + kk + tg);
                af[mt][0] = ap[0];
                af[mt][1] = ap[8*SSTRIDE];
                af[mt][2] = ap[4];
                af[mt][3] = ap[8*SSTRIDE + 4];
            }
            uint32_t bf[8][2];
#pragma unroll
            for (int nt = 0; nt < 8; nt++) {
                const uint32_t* bp = reinterpret_cast<const uint32_t*>(
                    Bs_ + (wn*64 + nt*8 + g)*SSTRIDE + kk + tg);
                bf[nt][0] = bp[0];
                bf[nt][1] = bp[4];
            }
#pragma unroll
            for (int mt = 0; mt < 2; mt++)
#pragma unroll
                for (int nt = 0; nt < 8; nt++)
                    mma_tf32(acc[mt][nt][0], acc[mt][nt][1], acc[mt][nt][2], acc[mt][nt][3],
                             af[mt][0], af[mt][1], af[mt][2], af[mt][3],
                             bf[nt][0], bf[nt][1]);
        }
    };

    load(0, 0); CP_COMMIT();
    load(1, 1); CP_COMMIT();

    for (int i = 0; i < NC; i++) {
        CP_WAIT1();
        __syncthreads();
        if (i + 2 < NC) load(i + 2, (i + 2) % NSTAGE);
        CP_COMMIT();
        compute(i % NSTAGE);
    }

#pragma unroll
    for (int mt = 0; mt < 2; mt++) {
        int r0 = wm*32 + mt*16 + g;
#pragma unroll
        for (int nt = 0; nt < 8; nt++) {
            int col = wn*64 + nt*8 + 2*tg;
            float d0 = acc[mt][nt][0], d1 = acc[mt][nt][1];
            float d2 = acc[mt][nt][2], d3 = acc[mt][nt][3];
            if (bias) { d0 += bias[col]; d1 += bias[col+1]; d2 += bias[col]; d3 += bias[col+1]; }
            if (round_out) {
                d0 = rna_tf32(d0); d1 = rna_tf32(d1);
                d2 = rna_tf32(d2); d3 = rna_tf32(d3);
            }
            if (col + 1 < nvalid) {
                *reinterpret_cast<float2*>(Cbase + (long)r0*crs + col)     = make_float2(d0, d1);
                *reinterpret_cast<float2*>(Cbase + (long)(r0+8)*crs + col) = make_float2(d2, d3);
            } else if (col < nvalid) {
                Cbase[(long)r0*crs + col]     = d0;
                Cbase[(long)(r0+8)*crs + col] = d2;
            }
        }
    }
}

// ---------------- GEMM wrappers ---------------------------------------------
__global__ __launch_bounds__(256) void k_in_proj()
{
    int dir = blockIdx.z, m0 = blockIdx.y*TM, n0 = blockIdx.x*TN;
    int b = m0 >> 11, l0 = m0 & 2047;
    const float* Abase; long ars;
    if (dir == 0) { Abase = g_xr + (size_t)m0*DM;                     ars =  DM; }
    else          { Abase = g_xr + ((size_t)b*LSEQ + (LSEQ-1-l0))*DM; ars = -(long)DM; }
    int nvalid = DPROJ - n0; if (nvalid > TN) nvalid = TN;
    gemm_tc(Abase, ars, &g_iwr[dir][0] + (size_t)n0*DM, DM, DM,
            nullptr, 0, nullptr, 0, 0,
            nvalid, &g_zx[dir][0][0][0] + (size_t)m0*DPROJ + n0, DPROJ, nullptr, false);
}

// M[dir][m, n] = sum_j pw[m, j + dir*768] * ow[j, n]   (768 x 1536)
__global__ __launch_bounds__(256) void k_mw()
{
    int dir = blockIdx.z, m0 = blockIdx.y*TM, n0 = blockIdx.x*TN;
    gemm_tc(g_pwr + (size_t)m0*(2*DM) + dir*DM, 2*DM,
            &g_owT[dir][0] + (size_t)n0*DM, DM, DM,
            nullptr, 0, nullptr, 0, 0,
            TN, &g_M[dir][0] + (size_t)m0*DIN + n0, DIN, nullptr, true);
}

// out[m, n] = sum_k y_f[m,k] Mf[n,k] + sum_k y_b[flip(m),k] Mb[n,k] + pb[n]
__global__ __launch_bounds__(256) void k_outf(const float* __restrict__ pb,
                                              float* __restrict__ out)
{
    int m0 = blockIdx.y*TM, n0 = blockIdx.x*TN;
    int b = m0 >> 11, l0 = m0 & 2047;
    gemm_tc(&g_y[0][0][0][0] + (size_t)m0*DIN, DIN,
            &g_M[0][0] + (size_t)n0*DIN, DIN, DIN,
            &g_y[1][0][0][0] + ((size_t)b*LSEQ + (LSEQ-1-l0))*DIN, -(long)DIN,
            &g_M[1][0] + (size_t)n0*DIN, DIN, DIN,
            TN, out + (size_t)m0*DM + n0, DM, pb + n0, false);
}

// ---------------- fused tf32 rounding pass ----------------------------------
#define NX  (NB*LSEQ*DM)
#define NIW (DPROJ*DM)
#define NPW (DM*2*DM)
__global__ void k_round_all(const float* __restrict__ x,
                            const float* __restrict__ fiw, const float* __restrict__ biw,
                            const float* __restrict__ pw,
                            float* __restrict__ xr, float* __restrict__ iwr,
                            float* __restrict__ pwr)
{
    long i = (long)blockIdx.x * 256 + threadIdx.x;
    if (i < NX)  { xr[i] = rna_tf32(x[i]); return; }
    i -= NX;
    if (i < NIW) { iwr[i] = rna_tf32(fiw[i]); return; }
    i -= NIW;
    if (i < NIW) { iwr[(long)NIW + i] = rna_tf32(biw[i]); return; }
    i -= NIW;
    if (i < NPW) { pwr[i] = rna_tf32(pw[i]); }
}

// ---------------- transpose + round out_w: (768,1536) -> (1536,768) ----------
__global__ __launch_bounds__(256) void k_transT(const float* __restrict__ fow,
                                                const float* __restrict__ bow)
{
    __shared__ float tile[32][33];
    int dir = blockIdx.z;
    const float* src = dir ? bow : fow;
    int n0 = blockIdx.x * 32;       // over DIN=1536
    int j0 = blockIdx.y * 32;       // over DM=768
    int tx = threadIdx.x & 31, ty = threadIdx.x >> 5;   // 32 x 8
#pragma unroll
    for (int q = 0; q < 4; q++)
        tile[ty + q*8][tx] = src[(size_t)(j0 + ty + q*8)*DIN + n0 + tx];
    __syncthreads();
#pragma unroll
    for (int q = 0; q < 4; q++)
        g_owT[dir][(size_t)(n0 + ty + q*8)*DM + j0 + tx] = rna_tf32(tile[tx][ty + q*8]);
}

// ---------------- exact fp32 dt path ----------------------------------------
__global__ __launch_bounds__(256) void k_dtx(const float* __restrict__ x,
        const float* __restrict__ fw, const float* __restrict__ bw,
        const float* __restrict__ fdb, const float* __restrict__ fA,
        const float* __restrict__ bdb, const float* __restrict__ bA)
{
    __shared__ float sx[8][DM];
    int t = threadIdx.x, lane = t & 31, w = t >> 5;
    long gr0 = (long)blockIdx.x * 8;
    for (int i = t; i < 8*(DM/4); i += 256) {
        int r = i / (DM/4), c4 = i % (DM/4);
        long gr = gr0 + r;
        int l = gr & 2047; long rr = gr >> 11; int b = (int)(rr & 1), dir = (int)(rr >> 1);
        long srow = (long)b*LSEQ + (dir ? (LSEQ-1-l) : l);
        *(float4*)&sx[r][c4*4] = *(const float4*)(x + srow*DM + c4*4);
    }
    __syncthreads();
    long gr = gr0 + w;
    int l = gr & 2047; long rr = gr >> 11; int b = (int)(rr & 1), dir = (int)(rr >> 1);
    const float* W  = dir ? bw  : fw;
    const float* db = dir ? bdb : fdb;
    const float* Al = dir ? bA  : fA;
    for (int h = 0; h < NH; h++) {
        const float* wr = W + (size_t)(DIN + CONVD + h)*DM;
        float s = 0.f;
        for (int k = lane*4; k < DM; k += 128) {
            float4 a = *(const float4*)&sx[w][k];
            float4 ww = *(const float4*)(wr + k);
            s += a.x*ww.x + a.y*ww.y + a.z*ww.z + a.w*ww.w;
        }
#pragma unroll
        for (int o = 16; o; o >>= 1) s += __shfl_xor_sync(0xffffffffu, s, o);
        if (lane == 0) {
            float raw = s + db[h];
            float dt = raw > 20.f ? raw : log1pf(expf(raw));
            g_dt[dir][b][l][h] = dt;
            g_dA[dir][b][l][h] = expf(-expf(Al[h]) * dt);
        }
    }
}

// ---------------- depthwise causal conv(4) + SiLU (4 l per thread) ----------
__global__ void k_conv(const float* __restrict__ fcw, const float* __restrict__ fcb,
                       const float* __restrict__ bcw, const float* __restrict__ bcb)
{
    long idx = (long)blockIdx.x * 256 + threadIdx.x;
    if (idx >= (long)2*NB*(LSEQ/4)*CONVD) return;
    int c = (int)(idx % CONVD);
    long r = idx / CONVD;
    int lq = (int)(r % (LSEQ/4));  r /= (LSEQ/4);
    int b = (int)(r % NB);
    int dir = (int)(r / NB);
    const float* cw = dir ? bcw : fcw;
    float w0 = cw[c*4+0], w1 = cw[c*4+1], w2 = cw[c*4+2], w3 = cw[c*4+3];
    float cb = (dir ? bcb : fcb)[c];
    int l0 = lq * 4;
    const float* col = &g_zx[dir][b][0][DIN + c];
    float v[7];
#pragma unroll
    for (int k = 0; k < 7; k++) {
        int l = l0 - 3 + k;
        v[k] = (l >= 0) ? col[(size_t)l*DPROJ] : 0.f;
    }
#pragma unroll
    for (int i = 0; i < 4; i++) {
        float s = cb + v[i]*w0 + v[i+1]*w1 + v[i+2]*w2 + v[i+3]*w3;
        g_xc[dir][b][l0 + i][c] = s / (1.f + expf(-s));
    }
}

// ---------------- chunked scan: phase A (local scans) ------------------------
__global__ __launch_bounds__(64) void k_scanA()
{
    int c = blockIdx.x, h = blockIdx.y;
    int bz = blockIdx.z; int b = bz & 1, dir = bz >> 1;
    int t = threadIdx.x;
    __shared__ float sx[32][HD];
    __shared__ __align__(16) float sB[32][DS];
    __shared__ float sdt[32], sdA[32];
    __shared__ __align__(16) float sC[32][DS];
    float hs[DS];
#pragma unroll
    for (int j = 0; j < DS; j++) hs[j] = 0.f;
    float cp = 1.f;
    int base = c * CT;

    for (int l0 = 0; l0 < CT; l0 += 32) {
#pragma unroll 4
        for (int j = 0; j < 32; j++)
            sx[j][t] = g_xc[dir][b][base + l0 + j][h*HD + t];
        for (int i = t; i < 32*DS; i += 64) {
            int s = i >> 4, j = i & 15;
            sB[s][j] = g_xc[dir][b][base + l0 + s][DIN + j];
            sC[s][j] = g_xc[dir][b][base + l0 + s][DIN + DS + j];
        }
        if (t < 32) {
            sdt[t] = g_dt[dir][b][base + l0 + t][h];
            sdA[t] = g_dA[dir][b][base + l0 + t][h];
        }
        __syncthreads();
#pragma unroll 2
        for (int s = 0; s < 32; s++) {
            float dAv = sdA[s];
            cp *= dAv;
            float xv  = sdt[s] * sx[s][t];
            float4 B0 = *(const float4*)&sB[s][0];
            float4 B1 = *(const float4*)&sB[s][4];
            float4 B2 = *(const float4*)&sB[s][8];
            float4 B3 = *(const float4*)&sB[s][12];
            float4 C0 = *(const float4*)&sC[s][0];
            float4 C1 = *(const float4*)&sC[s][4];
            float4 C2 = *(const float4*)&sC[s][8];
            float4 C3 = *(const float4*)&sC[s][12];
            float y = 0.f;
            hs[0]  = hs[0]*dAv  + xv*B0.x;  y += hs[0]*C0.x;
            hs[1]  = hs[1]*dAv  + xv*B0.y;  y += hs[1]*C0.y;
            hs[2]  = hs[2]*dAv  + xv*B0.z;  y += hs[2]*C0.z;
            hs[3]  = hs[3]*dAv  + xv*B0.w;  y += hs[3]*C0.w;
            hs[4]  = hs[4]*dAv  + xv*B1.x;  y += hs[4]*C1.x;
            hs[5]  = hs[5]*dAv  + xv*B1.y;  y += hs[5]*C1.y;
            hs[6]  = hs[6]*dAv  + xv*B1.z;  y += hs[6]*C1.z;
            hs[7]  = hs[7]*dAv  + xv*B1.w;  y += hs[7]*C1.w;
            hs[8]  = hs[8]*dAv  + xv*B2.x;  y += hs[8]*C2.x;
            hs[9]  = hs[9]*dAv  + xv*B2.y;  y += hs[9]*C2.y;
            hs[10] = hs[10]*dAv + xv*B2.z;  y += hs[10]*C2.z;
            hs[11] = hs[11]*dAv + xv*B2.w;  y += hs[11]*C2.w;
            hs[12] = hs[12]*dAv + xv*B3.x;  y += hs[12]*C3.x;
            hs[13] = hs[13]*dAv + xv*B3.y;  y += hs[13]*C3.y;
            hs[14] = hs[14]*dAv + xv*B3.z;  y += hs[14]*C3.z;
            hs[15] = hs[15]*dAv + xv*B3.w;  y += hs[15]*C3.w;
            g_y[dir][b][base + l0 + s][h*HD + t] = y;
        }
        __syncthreads();
    }
    float4* he = (float4*)&g_hend[dir][b][h][c][t][0];
    he[0] = make_float4(hs[0], hs[1], hs[2], hs[3]);
    he[1] = make_float4(hs[4], hs[5], hs[6], hs[7]);
    he[2] = make_float4(hs[8], hs[9], hs[10], hs[11]);
    he[3] = make_float4(hs[12], hs[13], hs[14], hs[15]);
    if (t == 0) g_cpe[dir][b][h][c] = cp;
}

// ---------------- chunked scan: phase B (chunk prefix) -----------------------
__global__ __launch_bounds__(64) void k_scanB()
{
    int h = blockIdx.x, b = blockIdx.y, dir = blockIdx.z;
    int t = threadIdx.x;
    float hin[DS];
#pragma unroll
    for (int j = 0; j < DS; j++) hin[j] = 0.f;
    for (int c = 0; c < NCH; c++) {
        float4* hp = (float4*)&g_hin[dir][b][h][c][t][0];
        hp[0] = make_float4(hin[0], hin[1], hin[2], hin[3]);
        hp[1] = make_float4(hin[4], hin[5], hin[6], hin[7]);
        hp[2] = make_float4(hin[8], hin[9], hin[10], hin[11]);
        hp[3] = make_float4(hin[12], hin[13], hin[14], hin[15]);
        float cpe = g_cpe[dir][b][h][c];
        const float4* he = (const float4*)&g_hend[dir][b][h][c][t][0];
        float4 e0 = he[0], e1 = he[1], e2 = he[2], e3 = he[3];
        hin[0]  = hin[0]*cpe  + e0.x;  hin[1]  = hin[1]*cpe  + e0.y;
        hin[2]  = hin[2]*cpe  + e0.z;  hin[3]  = hin[3]*cpe  + e0.w;
        hin[4]  = hin[4]*cpe  + e1.x;  hin[5]  = hin[5]*cpe  + e1.y;
        hin[6]  = hin[6]*cpe  + e1.z;  hin[7]  = hin[7]*cpe  + e1.w;
        hin[8]  = hin[8]*cpe  + e2.x;  hin[9]  = hin[9]*cpe  + e2.y;
        hin[10] = hin[10]*cpe + e2.z;  hin[11] = hin[11]*cpe + e2.w;
        hin[12] = hin[12]*cpe + e3.x;  hin[13] = hin[13]*cpe + e3.y;
        hin[14] = hin[14]*cpe + e3.z;  hin[15] = hin[15]*cpe + e3.w;
    }
}

// ---------------- chunked scan: phase C (carry-in correction) ----------------
__global__ __launch_bounds__(64) void k_scanC()
{
    int c = blockIdx.x + 1;
    int h = blockIdx.y;
    int bz = blockIdx.z; int b = bz & 1, dir = bz >> 1;
    int t = threadIdx.x;
    __shared__ __align__(16) float sC[32][DS];
    __shared__ float sdA[32];
    float hin[DS];
    {
        const float4* hp = (const float4*)&g_hin[dir][b][h][c][t][0];
        float4 a0 = hp[0], a1 = hp[1], a2 = hp[2], a3 = hp[3];
        hin[0]=a0.x; hin[1]=a0.y; hin[2]=a0.z; hin[3]=a0.w;
        hin[4]=a1.x; hin[5]=a1.y; hin[6]=a1.z; hin[7]=a1.w;
        hin[8]=a2.x; hin[9]=a2.y; hin[10]=a2.z; hin[11]=a2.w;
        hin[12]=a3.x; hin[13]=a3.y; hin[14]=a3.z; hin[15]=a3.w;
    }
    float cp = 1.f;
    int base = c * CT;
    for (int l0 = 0; l0 < CT; l0 += 32) {
        for (int i = t; i < 32*DS; i += 64) {
            int s = i >> 4, j = i & 15;
            sC[s][j] = g_xc[dir][b][base + l0 + s][DIN + DS + j];
        }
        if (t < 32) sdA[t] = g_dA[dir][b][base + l0 + t][h];
        __syncthreads();
#pragma unroll 4
        for (int s = 0; s < 32; s++) {
            cp *= sdA[s];
            float4 C0 = *(const float4*)&sC[s][0];
            float4 C1 = *(const float4*)&sC[s][4];
            float4 C2 = *(const float4*)&sC[s][8];
            float4 C3 = *(const float4*)&sC[s][12];
            float d = hin[0]*C0.x + hin[1]*C0.y + hin[2]*C0.z + hin[3]*C0.w
                    + hin[4]*C1.x + hin[5]*C1.y + hin[6]*C1.z + hin[7]*C1.w
                    + hin[8]*C2.x + hin[9]*C2.y + hin[10]*C2.z + hin[11]*C2.w
                    + hin[12]*C3.x + hin[13]*C3.y + hin[14]*C3.z + hin[15]*C3.w;
            g_y[dir][b][base + l0 + s][h*HD + t] += cp * d;
        }
        __syncthreads();
    }
}

// ---- y += Dp*xh; gate silu(z); RMSNorm; store tf32-rounded ------------------
__global__ void k_gate_norm(const float* __restrict__ fDp, const float* __restrict__ fnw,
                            const float* __restrict__ bDp, const float* __restrict__ bnw)
{
    int row = blockIdx.x;
    int l = row % LSEQ;
    int r = row / LSEQ;
    int b = r % NB;
    int dir = r / NB;
    const float* Dp = dir ? bDp : fDp;
    const float* nw = dir ? bnw : fnw;
    float vals[6];
    float sq = 0.f;
#pragma unroll
    for (int ii = 0; ii < 6; ii++) {
        int i = threadIdx.x + ii*256;
        int hh = i >> 6;
        float xh = g_xc[dir][b][l][i];
        float yv = g_y[dir][b][l][i] + Dp[hh]*xh;
        float z  = g_zx[dir][b][l][i];
        yv *= z / (1.f + expf(-z));
        vals[ii] = yv;
        sq += yv*yv;
    }
#pragma unroll
    for (int o = 16; o; o >>= 1) sq += __shfl_xor_sync(0xffffffffu, sq, o);
    __shared__ float ssum[8];
    __shared__ float sscale;
    int w = threadIdx.x >> 5;
    if ((threadIdx.x & 31) == 0) ssum[w] = sq;
    __syncthreads();
    if (threadIdx.x == 0) {
        float tot = 0.f;
        for (int i = 0; i < 8; i++) tot += ssum[i];
        sscale = rsqrtf(tot/(float)DIN + 1e-5f);
    }
    __syncthreads();
    float scale = sscale;
#pragma unroll
    for (int ii = 0; ii < 6; ii++) {
        int i = threadIdx.x + ii*256;
        g_y[dir][b][l][i] = rna_tf32(vals[ii]*scale*nw[i]);
    }
}

// ---------------- launch -----------------------------------------------------
extern "C" void kernel_launch(void* const* d_in, const int* in_sizes, int n_in,
                              void* d_out, int out_size)
{
    const float* x      = (const float*)d_in[0];
    const float* pw     = (const float*)d_in[1];
    const float* pb     = (const float*)d_in[2];
    const float* f_in_w = (const float*)d_in[3];
    const float* f_cw   = (const float*)d_in[4];
    const float* f_cb   = (const float*)d_in[5];
    const float* f_db   = (const float*)d_in[6];
    const float* f_Al   = (const float*)d_in[7];
    const float* f_Dp   = (const float*)d_in[8];
    const float* f_nw   = (const float*)d_in[9];
    const float* f_ow   = (const float*)d_in[10];
    const float* b_in_w = (const float*)d_in[11];
    const float* b_cw   = (const float*)d_in[12];
    const float* b_cb   = (const float*)d_in[13];
    const float* b_db   = (const float*)d_in[14];
    const float* b_Al   = (const float*)d_in[15];
    const float* b_Dp   = (const float*)d_in[16];
    const float* b_nw   = (const float*)d_in[17];
    const float* b_ow   = (const float*)d_in[18];
    float* out = (float*)d_out;

    cudaFuncSetAttribute(k_in_proj, cudaFuncAttributeMaxDynamicSharedMemorySize, DSMEM);
    cudaFuncSetAttribute(k_mw,      cudaFuncAttributeMaxDynamicSharedMemorySize, DSMEM);
    cudaFuncSetAttribute(k_outf,    cudaFuncAttributeMaxDynamicSharedMemorySize, DSMEM);

    float* xr  = nullptr; cudaGetSymbolAddress((void**)&xr,  g_xr);
    float* iwr = nullptr; cudaGetSymbolAddress((void**)&iwr, g_iwr);
    float* pwr = nullptr; cudaGetSymbolAddress((void**)&pwr, g_pwr);

    // side streams (created once; every call enqueues the identical DAG)
    static cudaStream_t s_dtx = nullptr, s_mw = nullptr;
    static cudaEvent_t e_fork0 = nullptr, e_fork1 = nullptr, e_dtx = nullptr, e_mw = nullptr;
    if (s_dtx == nullptr) {
        cudaStreamCreateWithFlags(&s_dtx, cudaStreamNonBlocking);
        cudaStreamCreateWithFlags(&s_mw,  cudaStreamNonBlocking);
        cudaEventCreateWithFlags(&e_fork0, cudaEventDisableTiming);
        cudaEventCreateWithFlags(&e_fork1, cudaEventDisableTiming);
        cudaEventCreateWithFlags(&e_dtx,   cudaEventDisableTiming);
        cudaEventCreateWithFlags(&e_mw,    cudaEventDisableTiming);
    }

    dim3 blk(256);

    // fork: dtx is independent of all rounding work
    cudaEventRecord(e_fork0, 0);
    cudaStreamWaitEvent(s_dtx, e_fork0, 0);
    k_dtx<<<2*NB*LSEQ/8, blk, 0, s_dtx>>>(x, f_in_w, b_in_w, f_db, f_Al, b_db, b_Al);
    cudaEventRecord(e_dtx, s_dtx);

    long ntot = (long)NX + 2*NIW + NPW;
    k_round_all<<<(unsigned)((ntot + 255)/256), blk>>>(x, f_in_w, b_in_w, pw, xr, iwr, pwr);
    k_transT<<<dim3(DIN/32, DM/32, 2), blk>>>(f_ow, b_ow);

    // fork: mw needs round_all (pwr) + transT (owT); runs alongside in_proj..gate
    cudaEventRecord(e_fork1, 0);
    cudaStreamWaitEvent(s_mw, e_fork1, 0);
    k_mw<<<dim3(DIN/TN, DM/TM, 2), blk, DSMEM, s_mw>>>();
    cudaEventRecord(e_mw, s_mw);

    k_in_proj<<<dim3((DPROJ + TN - 1)/TN, (NB*LSEQ)/TM, 2), blk, DSMEM>>>();

    long nconv = (long)2*NB*(LSEQ/4)*CONVD;
    k_conv<<<(unsigned)((nconv + 255)/256), blk>>>(f_cw, f_cb, b_cw, b_cb);

    cudaStreamWaitEvent(0, e_dtx, 0);   // join dtx before scan
    k_scanA<<<dim3(NCH, NH, NB*2), 64>>>();
    k_scanB<<<dim3(NH, NB, 2), 64>>>();
    k_scanC<<<dim3(NCH - 1, NH, NB*2), 64>>>();

    k_gate_norm<<<2*NB*LSEQ, blk>>>(f_Dp, f_nw, b_Dp, b_nw);

    cudaStreamWaitEvent(0, e_mw, 0);    // join mw before final GEMM
    k_outf<<<dim3(DM/TN, (NB*LSEQ)/TM, 1), blk, DSMEM>>>(pb, out);
}

// round 14
// speedup vs baseline: 1.2411x; 1.0046x over previous
#include <cuda_runtime.h>
#include <math.h>
#include <stdint.h>

#define LSEQ  2048
#define NB    2
#define DM    768
#define DIN   1536
#define NH    24
#define HD    64
#define DS    16
#define CONVD 1568
#define DPROJ 3128

#define NCH 16
#define CT  (LSEQ/NCH)

#define TM 128
#define TN 128
#define GK 32
#define SSTRIDE 36
#define STAGEF (128*SSTRIDE)            // floats per operand per stage
#define STAGEB (2*STAGEF*4)             // bytes per stage (A+B)
#define NSTAGE 3
#define DSMEM  (NSTAGE*STAGEB)          // 110592 B

// ---------------- scratch (device globals) ----------------------------------
__device__ float g_zx[2][NB][LSEQ][DPROJ];
__device__ float g_xc[2][NB][LSEQ][CONVD];
__device__ float g_dt[2][NB][LSEQ][NH];
__device__ float g_dA[2][NB][LSEQ][NH];
__device__ float g_y [2][NB][LSEQ][DIN];
__device__ float g_hend[2][NB][NH][NCH][HD][DS];
__device__ float g_hin [2][NB][NH][NCH][HD][DS];
__device__ float g_cpe [2][NB][NH][NCH];
// tf32-pre-rounded GEMM operands
__device__ float g_xr [NB*LSEQ*DM];
__device__ float g_iwr[2][DPROJ*DM];
__device__ float g_pwr[DM*2*DM];
__device__ float g_owT[2][DIN*DM];
__device__ float g_M  [2][DM*DIN];

// ---------------- helpers ----------------------------------------------------
__device__ __forceinline__ uint32_t s2u(const void* p){
    uint32_t a;
    asm("{ .reg .u64 t; cvta.to.shared.u64 t, %1; cvt.u32.u64 %0, t; }" : "=r"(a) : "l"(p));
    return a;
}
__device__ __forceinline__ float rna_tf32(float f){
    uint32_t t; asm("cvt.rna.tf32.f32 %0, %1;" : "=r"(t) : "f"(f));
    return __uint_as_float(t);
}
__device__ __forceinline__ void cpa16(uint32_t dst, const float* src, bool p){
    int sz = p ? 16 : 0;
    asm volatile("cp.async.cg.shared.global [%0], [%1], 16, %2;"
                 :: "r"(dst), "l"(src), "r"(sz) : "memory");
}
#define CP_COMMIT() asm volatile("cp.async.commit_group;" ::: "memory")
#define CP_WAIT1()  asm volatile("cp.async.wait_group 1;" ::: "memory")
__device__ __forceinline__ void mma_tf32(float& d0, float& d1, float& d2, float& d3,
                                         uint32_t a0, uint32_t a1, uint32_t a2, uint32_t a3,
                                         uint32_t b0, uint32_t b1){
    asm volatile("mma.sync.aligned.m16n8k8.row.col.f32.tf32.tf32.f32 "
                 "{%0,%1,%2,%3}, {%4,%5,%6,%7}, {%8,%9}, {%0,%1,%2,%3};"
                 : "+f"(d0), "+f"(d1), "+f"(d2), "+f"(d3)
                 : "r"(a0), "r"(a1), "r"(a2), "r"(a3), "r"(b0), "r"(b1));
}

// ---------------- tf32 mma.sync GEMM core (cp.async 3-stage, 2-pass) ---------
// Operands MUST be pre-rounded to tf32.
// acc[m,n] = sum_k A0[m,k]*B0[n,k]  (+ sum_k A1[m,k]*B1[n,k] if K1>0)
__device__ __forceinline__ void gemm_tc(
    const float* __restrict__ A0, long lda0, const float* __restrict__ B0, int ldb0, int K0,
    const float* __restrict__ A1, long lda1, const float* __restrict__ B1, int ldb1, int K1,
    int nvalid, float* __restrict__ Cbase, long crs,
    const float* __restrict__ bias, bool round_out)
{
    extern __shared__ float dsm[];
    const uint32_t smBase = s2u(dsm);
    const int tid  = threadIdx.x;
    const int lane = tid & 31;
    const int wid  = tid >> 5;
    const int wm   = wid & 3;
    const int wn   = wid >> 2;
    const int g    = lane >> 2;
    const int tg   = lane & 3;
    const int lr   = tid >> 3;
    const int lc   = tid & 7;

    float acc[2][8][4];
#pragma unroll
    for (int mt = 0; mt < 2; mt++)
#pragma unroll
        for (int nt = 0; nt < 8; nt++)
#pragma unroll
            for (int q = 0; q < 4; q++) acc[mt][nt][q] = 0.f;

    const int NC0 = K0 / GK;
    const int NC  = NC0 + K1 / GK;

    auto load = [&](int chunk, int s){
        const float* Ab; long la; const float* Bb; int lb; int kt;
        if (chunk < NC0) { Ab = A0; la = lda0; Bb = B0; lb = ldb0; kt = chunk*GK; }
        else             { Ab = A1; la = lda1; Bb = B1; lb = ldb1; kt = (chunk-NC0)*GK; }
        uint32_t stA = smBase + s*STAGEB;
        uint32_t stB = stA + STAGEF*4;
#pragma unroll
        for (int j = 0; j < 4; j++) {
            int r = lr + j*32;
            cpa16(stA + (uint32_t)(r*SSTRIDE + lc*4)*4, Ab + (long)r*la + kt + lc*4, true);
            cpa16(stB + (uint32_t)(r*SSTRIDE + lc*4)*4, Bb + (long)r*lb + kt + lc*4, r < nvalid);
        }
    };
    auto compute = [&](int s){
        const float* As_ = dsm + s*(2*STAGEF);
        const float* Bs_ = As_ + STAGEF;
#pragma unroll
        for (int kk = 0; kk < GK; kk += 8) {
            uint32_t af[2][4];
#pragma unroll
            for (int mt = 0; mt < 2; mt++) {
                const uint32_t* ap = reinterpret_cast<const uint32_t*>(
                    As_ + (wm*32 + mt*16 + g)*SSTRIDE + kk + tg);
                af[mt][0] = ap[0];
                af[mt][1] = ap[8*SSTRIDE];
                af[mt][2] = ap[4];
                af[mt][3] = ap[8*SSTRIDE + 4];
            }
            uint32_t bf[8][2];
#pragma unroll
            for (int nt = 0; nt < 8; nt++) {
                const uint32_t* bp = reinterpret_cast<const uint32_t*>(
                    Bs_ + (wn*64 + nt*8 + g)*SSTRIDE + kk + tg);
                bf[nt][0] = bp[0];
                bf[nt][1] = bp[4];
            }
#pragma unroll
            for (int mt = 0; mt < 2; mt++)
#pragma unroll
                for (int nt = 0; nt < 8; nt++)
                    mma_tf32(acc[mt][nt][0], acc[mt][nt][1], acc[mt][nt][2], acc[mt][nt][3],
                             af[mt][0], af[mt][1], af[mt][2], af[mt][3],
                             bf[nt][0], bf[nt][1]);
        }
    };

    load(0, 0); CP_COMMIT();
    load(1, 1); CP_COMMIT();

    for (int i = 0; i < NC; i++) {
        CP_WAIT1();
        __syncthreads();
        if (i + 2 < NC) load(i + 2, (i + 2) % NSTAGE);
        CP_COMMIT();
        compute(i % NSTAGE);
    }

#pragma unroll
    for (int mt = 0; mt < 2; mt++) {
        int r0 = wm*32 + mt*16 + g;
#pragma unroll
        for (int nt = 0; nt < 8; nt++) {
            int col = wn*64 + nt*8 + 2*tg;
            float d0 = acc[mt][nt][0], d1 = acc[mt][nt][1];
            float d2 = acc[mt][nt][2], d3 = acc[mt][nt][3];
            if (bias) { d0 += bias[col]; d1 += bias[col+1]; d2 += bias[col]; d3 += bias[col+1]; }
            if (round_out) {
                d0 = rna_tf32(d0); d1 = rna_tf32(d1);
                d2 = rna_tf32(d2); d3 = rna_tf32(d3);
            }
            if (col + 1 < nvalid) {
                *reinterpret_cast<float2*>(Cbase + (long)r0*crs + col)     = make_float2(d0, d1);
                *reinterpret_cast<float2*>(Cbase + (long)(r0+8)*crs + col) = make_float2(d2, d3);
            } else if (col < nvalid) {
                Cbase[(long)r0*crs + col]     = d0;
                Cbase[(long)(r0+8)*crs + col] = d2;
            }
        }
    }
}

// ---------------- GEMM wrappers ---------------------------------------------
// in_proj over an n-tile subrange [ntile0, ntile0+gridDim.x)
__global__ __launch_bounds__(256) void k_in_proj(int ntile0)
{
    int dir = blockIdx.z, m0 = blockIdx.y*TM, n0 = (blockIdx.x + ntile0)*TN;
    int b = m0 >> 11, l0 = m0 & 2047;
    const float* Abase; long ars;
    if (dir == 0) { Abase = g_xr + (size_t)m0*DM;                     ars =  DM; }
    else          { Abase = g_xr + ((size_t)b*LSEQ + (LSEQ-1-l0))*DM; ars = -(long)DM; }
    int nvalid = DPROJ - n0; if (nvalid > TN) nvalid = TN;
    gemm_tc(Abase, ars, &g_iwr[dir][0] + (size_t)n0*DM, DM, DM,
            nullptr, 0, nullptr, 0, 0,
            nvalid, &g_zx[dir][0][0][0] + (size_t)m0*DPROJ + n0, DPROJ, nullptr, false);
}

// M[dir][m, n] = sum_j pw[m, j + dir*768] * ow[j, n]   (768 x 1536)
__global__ __launch_bounds__(256) void k_mw()
{
    int dir = blockIdx.z, m0 = blockIdx.y*TM, n0 = blockIdx.x*TN;
    gemm_tc(g_pwr + (size_t)m0*(2*DM) + dir*DM, 2*DM,
            &g_owT[dir][0] + (size_t)n0*DM, DM, DM,
            nullptr, 0, nullptr, 0, 0,
            TN, &g_M[dir][0] + (size_t)m0*DIN + n0, DIN, nullptr, true);
}

// out[m, n] = sum_k y_f[m,k] Mf[n,k] + sum_k y_b[flip(m),k] Mb[n,k] + pb[n]
__global__ __launch_bounds__(256) void k_outf(const float* __restrict__ pb,
                                              float* __restrict__ out)
{
    int m0 = blockIdx.y*TM, n0 = blockIdx.x*TN;
    int b = m0 >> 11, l0 = m0 & 2047;
    gemm_tc(&g_y[0][0][0][0] + (size_t)m0*DIN, DIN,
            &g_M[0][0] + (size_t)n0*DIN, DIN, DIN,
            &g_y[1][0][0][0] + ((size_t)b*LSEQ + (LSEQ-1-l0))*DIN, -(long)DIN,
            &g_M[1][0] + (size_t)n0*DIN, DIN, DIN,
            TN, out + (size_t)m0*DM + n0, DM, pb + n0, false);
}

// ---------------- fused tf32 rounding pass ----------------------------------
#define NX  (NB*LSEQ*DM)
#define NIW (DPROJ*DM)
#define NPW (DM*2*DM)
__global__ void k_round_all(const float* __restrict__ x,
                            const float* __restrict__ fiw, const float* __restrict__ biw,
                            const float* __restrict__ pw,
                            float* __restrict__ xr, float* __restrict__ iwr,
                            float* __restrict__ pwr)
{
    long i = (long)blockIdx.x * 256 + threadIdx.x;
    if (i < NX)  { xr[i] = rna_tf32(x[i]); return; }
    i -= NX;
    if (i < NIW) { iwr[i] = rna_tf32(fiw[i]); return; }
    i -= NIW;
    if (i < NIW) { iwr[(long)NIW + i] = rna_tf32(biw[i]); return; }
    i -= NIW;
    if (i < NPW) { pwr[i] = rna_tf32(pw[i]); }
}

// ---------------- transpose + round out_w: (768,1536) -> (1536,768) ----------
__global__ __launch_bounds__(256) void k_transT(const float* __restrict__ fow,
                                                const float* __restrict__ bow)
{
    __shared__ float tile[32][33];
    int dir = blockIdx.z;
    const float* src = dir ? bow : fow;
    int n0 = blockIdx.x * 32;       // over DIN=1536
    int j0 = blockIdx.y * 32;       // over DM=768
    int tx = threadIdx.x & 31, ty = threadIdx.x >> 5;   // 32 x 8
#pragma unroll
    for (int q = 0; q < 4; q++)
        tile[ty + q*8][tx] = src[(size_t)(j0 + ty + q*8)*DIN + n0 + tx];
    __syncthreads();
#pragma unroll
    for (int q = 0; q < 4; q++)
        g_owT[dir][(size_t)(n0 + ty + q*8)*DM + j0 + tx] = rna_tf32(tile[tx][ty + q*8]);
}

// ---------------- exact fp32 dt path ----------------------------------------
__global__ __launch_bounds__(256) void k_dtx(const float* __restrict__ x,
        const float* __restrict__ fw, const float* __restrict__ bw,
        const float* __restrict__ fdb, const float* __restrict__ fA,
        const float* __restrict__ bdb, const float* __restrict__ bA)
{
    __shared__ float sx[8][DM];
    int t = threadIdx.x, lane = t & 31, w = t >> 5;
    long gr0 = (long)blockIdx.x * 8;
    for (int i = t; i < 8*(DM/4); i += 256) {
        int r = i / (DM/4), c4 = i % (DM/4);
        long gr = gr0 + r;
        int l = gr & 2047; long rr = gr >> 11; int b = (int)(rr & 1), dir = (int)(rr >> 1);
        long srow = (long)b*LSEQ + (dir ? (LSEQ-1-l) : l);
        *(float4*)&sx[r][c4*4] = *(const float4*)(x + srow*DM + c4*4);
    }
    __syncthreads();
    long gr = gr0 + w;
    int l = gr & 2047; long rr = gr >> 11; int b = (int)(rr & 1), dir = (int)(rr >> 1);
    const float* W  = dir ? bw  : fw;
    const float* db = dir ? bdb : fdb;
    const float* Al = dir ? bA  : fA;
    for (int h = 0; h < NH; h++) {
        const float* wr = W + (size_t)(DIN + CONVD + h)*DM;
        float s = 0.f;
        for (int k = lane*4; k < DM; k += 128) {
            float4 a = *(const float4*)&sx[w][k];
            float4 ww = *(const float4*)(wr + k);
            s += a.x*ww.x + a.y*ww.y + a.z*ww.z + a.w*ww.w;
        }
#pragma unroll
        for (int o = 16; o; o >>= 1) s += __shfl_xor_sync(0xffffffffu, s, o);
        if (lane == 0) {
            float raw = s + db[h];
            float dt = raw > 20.f ? raw : log1pf(expf(raw));
            g_dt[dir][b][l][h] = dt;
            g_dA[dir][b][l][h] = expf(-expf(Al[h]) * dt);
        }
    }
}

// ---------------- depthwise causal conv(4) + SiLU (4 l per thread) ----------
__global__ void k_conv(const float* __restrict__ fcw, const float* __restrict__ fcb,
                       const float* __restrict__ bcw, const float* __restrict__ bcb)
{
    long idx = (long)blockIdx.x * 256 + threadIdx.x;
    if (idx >= (long)2*NB*(LSEQ/4)*CONVD) return;
    int c = (int)(idx % CONVD);
    long r = idx / CONVD;
    int lq = (int)(r % (LSEQ/4));  r /= (LSEQ/4);
    int b = (int)(r % NB);
    int dir = (int)(r / NB);
    const float* cw = dir ? bcw : fcw;
    float w0 = cw[c*4+0], w1 = cw[c*4+1], w2 = cw[c*4+2], w3 = cw[c*4+3];
    float cb = (dir ? bcb : fcb)[c];
    int l0 = lq * 4;
    const float* col = &g_zx[dir][b][0][DIN + c];
    float v[7];
#pragma unroll
    for (int k = 0; k < 7; k++) {
        int l = l0 - 3 + k;
        v[k] = (l >= 0) ? col[(size_t)l*DPROJ] : 0.f;
    }
#pragma unroll
    for (int i = 0; i < 4; i++) {
        float s = cb + v[i]*w0 + v[i+1]*w1 + v[i+2]*w2 + v[i+3]*w3;
        g_xc[dir][b][l0 + i][c] = s / (1.f + expf(-s));
    }
}

// ---------------- chunked scan: phase A (local scans) ------------------------
__global__ __launch_bounds__(64) void k_scanA()
{
    int c = blockIdx.x, h = blockIdx.y;
    int bz = blockIdx.z; int b = bz & 1, dir = bz >> 1;
    int t = threadIdx.x;
    __shared__ float sx[32][HD];
    __shared__ __align__(16) float sB[32][DS];
    __shared__ float sdt[32], sdA[32];
    __shared__ __align__(16) float sC[32][DS];
    float hs[DS];
#pragma unroll
    for (int j = 0; j < DS; j++) hs[j] = 0.f;
    float cp = 1.f;
    int base = c * CT;

    for (int l0 = 0; l0 < CT; l0 += 32) {
#pragma unroll 4
        for (int j = 0; j < 32; j++)
            sx[j][t] = g_xc[dir][b][base + l0 + j][h*HD + t];
        for (int i = t; i < 32*DS; i += 64) {
            int s = i >> 4, j = i & 15;
            sB[s][j] = g_xc[dir][b][base + l0 + s][DIN + j];
            sC[s][j] = g_xc[dir][b][base + l0 + s][DIN + DS + j];
        }
        if (t < 32) {
            sdt[t] = g_dt[dir][b][base + l0 + t][h];
            sdA[t] = g_dA[dir][b][base + l0 + t][h];
        }
        __syncthreads();
#pragma unroll 2
        for (int s = 0; s < 32; s++) {
            float dAv = sdA[s];
            cp *= dAv;
            float xv  = sdt[s] * sx[s][t];
            float4 B0 = *(const float4*)&sB[s][0];
            float4 B1 = *(const float4*)&sB[s][4];
            float4 B2 = *(const float4*)&sB[s][8];
            float4 B3 = *(const float4*)&sB[s][12];
            float4 C0 = *(const float4*)&sC[s][0];
            float4 C1 = *(const float4*)&sC[s][4];
            float4 C2 = *(const float4*)&sC[s][8];
            float4 C3 = *(const float4*)&sC[s][12];
            float y = 0.f;
            hs[0]  = hs[0]*dAv  + xv*B0.x;  y += hs[0]*C0.x;
            hs[1]  = hs[1]*dAv  + xv*B0.y;  y += hs[1]*C0.y;
            hs[2]  = hs[2]*dAv  + xv*B0.z;  y += hs[2]*C0.z;
            hs[3]  = hs[3]*dAv  + xv*B0.w;  y += hs[3]*C0.w;
            hs[4]  = hs[4]*dAv  + xv*B1.x;  y += hs[4]*C1.x;
            hs[5]  = hs[5]*dAv  + xv*B1.y;  y += hs[5]*C1.y;
            hs[6]  = hs[6]*dAv  + xv*B1.z;  y += hs[6]*C1.z;
            hs[7]  = hs[7]*dAv  + xv*B1.w;  y += hs[7]*C1.w;
            hs[8]  = hs[8]*dAv  + xv*B2.x;  y += hs[8]*C2.x;
            hs[9]  = hs[9]*dAv  + xv*B2.y;  y += hs[9]*C2.y;
            hs[10] = hs[10]*dAv + xv*B2.z;  y += hs[10]*C2.z;
            hs[11] = hs[11]*dAv + xv*B2.w;  y += hs[11]*C2.w;
            hs[12] = hs[12]*dAv + xv*B3.x;  y += hs[12]*C3.x;
            hs[13] = hs[13]*dAv + xv*B3.y;  y += hs[13]*C3.y;
            hs[14] = hs[14]*dAv + xv*B3.z;  y += hs[14]*C3.z;
            hs[15] = hs[15]*dAv + xv*B3.w;  y += hs[15]*C3.w;
            g_y[dir][b][base + l0 + s][h*HD + t] = y;
        }
        __syncthreads();
    }
    float4* he = (float4*)&g_hend[dir][b][h][c][t][0];
    he[0] = make_float4(hs[0], hs[1], hs[2], hs[3]);
    he[1] = make_float4(hs[4], hs[5], hs[6], hs[7]);
    he[2] = make_float4(hs[8], hs[9], hs[10], hs[11]);
    he[3] = make_float4(hs[12], hs[13], hs[14], hs[15]);
    if (t == 0) g_cpe[dir][b][h][c] = cp;
}

// ---------------- chunked scan: phase B (chunk prefix) -----------------------
__global__ __launch_bounds__(64) void k_scanB()
{
    int h = blockIdx.x, b = blockIdx.y, dir = blockIdx.z;
    int t = threadIdx.x;
    float hin[DS];
#pragma unroll
    for (int j = 0; j < DS; j++) hin[j] = 0.f;
    for (int c = 0; c < NCH; c++) {
        float4* hp = (float4*)&g_hin[dir][b][h][c][t][0];
        hp[0] = make_float4(hin[0], hin[1], hin[2], hin[3]);
        hp[1] = make_float4(hin[4], hin[5], hin[6], hin[7]);
        hp[2] = make_float4(hin[8], hin[9], hin[10], hin[11]);
        hp[3] = make_float4(hin[12], hin[13], hin[14], hin[15]);
        float cpe = g_cpe[dir][b][h][c];
        const float4* he = (const float4*)&g_hend[dir][b][h][c][t][0];
        float4 e0 = he[0], e1 = he[1], e2 = he[2], e3 = he[3];
        hin[0]  = hin[0]*cpe  + e0.x;  hin[1]  = hin[1]*cpe  + e0.y;
        hin[2]  = hin[2]*cpe  + e0.z;  hin[3]  = hin[3]*cpe  + e0.w;
        hin[4]  = hin[4]*cpe  + e1.x;  hin[5]  = hin[5]*cpe  + e1.y;
        hin[6]  = hin[6]*cpe  + e1.z;  hin[7]  = hin[7]*cpe  + e1.w;
        hin[8]  = hin[8]*cpe  + e2.x;  hin[9]  = hin[9]*cpe  + e2.y;
        hin[10] = hin[10]*cpe + e2.z;  hin[11] = hin[11]*cpe + e2.w;
        hin[12] = hin[12]*cpe + e3.x;  hin[13] = hin[13]*cpe + e3.y;
        hin[14] = hin[14]*cpe + e3.z;  hin[15] = hin[15]*cpe + e3.w;
    }
}

// ---------------- chunked scan: phase C (carry-in correction) ----------------
__global__ __launch_bounds__(64) void k_scanC()
{
    int c = blockIdx.x + 1;
    int h = blockIdx.y;
    int bz = blockIdx.z; int b = bz & 1, dir = bz >> 1;
    int t = threadIdx.x;
    __shared__ __align__(16) float sC[32][DS];
    __shared__ float sdA[32];
    float hin[DS];
    {
        const float4* hp = (const float4*)&g_hin[dir][b][h][c][t][0];
        float4 a0 = hp[0], a1 = hp[1], a2 = hp[2], a3 = hp[3];
        hin[0]=a0.x; hin[1]=a0.y; hin[2]=a0.z; hin[3]=a0.w;
        hin[4]=a1.x; hin[5]=a1.y; hin[6]=a1.z; hin[7]=a1.w;
        hin[8]=a2.x; hin[9]=a2.y; hin[10]=a2.z; hin[11]=a2.w;
        hin[12]=a3.x; hin[13]=a3.y; hin[14]=a3.z; hin[15]=a3.w;
    }
    float cp = 1.f;
    int base = c * CT;
    for (int l0 = 0; l0 < CT; l0 += 32) {
        for (int i = t; i < 32*DS; i += 64) {
            int s = i >> 4, j = i & 15;
            sC[s][j] = g_xc[dir][b][base + l0 + s][DIN + DS + j];
        }
        if (t < 32) sdA[t] = g_dA[dir][b][base + l0 + t][h];
        __syncthreads();
#pragma unroll 4
        for (int s = 0; s < 32; s++) {
            cp *= sdA[s];
            float4 C0 = *(const float4*)&sC[s][0];
            float4 C1 = *(const float4*)&sC[s][4];
            float4 C2 = *(const float4*)&sC[s][8];
            float4 C3 = *(const float4*)&sC[s][12];
            float d = hin[0]*C0.x + hin[1]*C0.y + hin[2]*C0.z + hin[3]*C0.w
                    + hin[4]*C1.x + hin[5]*C1.y + hin[6]*C1.z + hin[7]*C1.w
                    + hin[8]*C2.x + hin[9]*C2.y + hin[10]*C2.z + hin[11]*C2.w
                    + hin[12]*C3.x + hin[13]*C3.y + hin[14]*C3.z + hin[15]*C3.w;
            g_y[dir][b][base + l0 + s][h*HD + t] += cp * d;
        }
        __syncthreads();
    }
}

// ---- y += Dp*xh; gate silu(z); RMSNorm; store tf32-rounded ------------------
__global__ void k_gate_norm(const float* __restrict__ fDp, const float* __restrict__ fnw,
                            const float* __restrict__ bDp, const float* __restrict__ bnw)
{
    int row = blockIdx.x;
    int l = row % LSEQ;
    int r = row / LSEQ;
    int b = r % NB;
    int dir = r / NB;
    const float* Dp = dir ? bDp : fDp;
    const float* nw = dir ? bnw : fnw;
    float vals[6];
    float sq = 0.f;
#pragma unroll
    for (int ii = 0; ii < 6; ii++) {
        int i = threadIdx.x + ii*256;
        int hh = i >> 6;
        float xh = g_xc[dir][b][l][i];
        float yv = g_y[dir][b][l][i] + Dp[hh]*xh;
        float z  = g_zx[dir][b][l][i];
        yv *= z / (1.f + expf(-z));
        vals[ii] = yv;
        sq += yv*yv;
    }
#pragma unroll
    for (int o = 16; o; o >>= 1) sq += __shfl_xor_sync(0xffffffffu, sq, o);
    __shared__ float ssum[8];
    __shared__ float sscale;
    int w = threadIdx.x >> 5;
    if ((threadIdx.x & 31) == 0) ssum[w] = sq;
    __syncthreads();
    if (threadIdx.x == 0) {
        float tot = 0.f;
        for (int i = 0; i < 8; i++) tot += ssum[i];
        sscale = rsqrtf(tot/(float)DIN + 1e-5f);
    }
    __syncthreads();
    float scale = sscale;
#pragma unroll
    for (int ii = 0; ii < 6; ii++) {
        int i = threadIdx.x + ii*256;
        g_y[dir][b][l][i] = rna_tf32(vals[ii]*scale*nw[i]);
    }
}

// ---------------- launch -----------------------------------------------------
extern "C" void kernel_launch(void* const* d_in, const int* in_sizes, int n_in,
                              void* d_out, int out_size)
{
    const float* x      = (const float*)d_in[0];
    const float* pw     = (const float*)d_in[1];
    const float* pb     = (const float*)d_in[2];
    const float* f_in_w = (const float*)d_in[3];
    const float* f_cw   = (const float*)d_in[4];
    const float* f_cb   = (const float*)d_in[5];
    const float* f_db   = (const float*)d_in[6];
    const float* f_Al   = (const float*)d_in[7];
    const float* f_Dp   = (const float*)d_in[8];
    const float* f_nw   = (const float*)d_in[9];
    const float* f_ow   = (const float*)d_in[10];
    const float* b_in_w = (const float*)d_in[11];
    const float* b_cw   = (const float*)d_in[12];
    const float* b_cb   = (const float*)d_in[13];
    const float* b_db   = (const float*)d_in[14];
    const float* b_Al   = (const float*)d_in[15];
    const float* b_Dp   = (const float*)d_in[16];
    const float* b_nw   = (const float*)d_in[17];
    const float* b_ow   = (const float*)d_in[18];
    float* out = (float*)d_out;

    cudaFuncSetAttribute(k_in_proj, cudaFuncAttributeMaxDynamicSharedMemorySize, DSMEM);
    cudaFuncSetAttribute(k_mw,      cudaFuncAttributeMaxDynamicSharedMemorySize, DSMEM);
    cudaFuncSetAttribute(k_outf,    cudaFuncAttributeMaxDynamicSharedMemorySize, DSMEM);

    float* xr  = nullptr; cudaGetSymbolAddress((void**)&xr,  g_xr);
    float* iwr = nullptr; cudaGetSymbolAddress((void**)&iwr, g_iwr);
    float* pwr = nullptr; cudaGetSymbolAddress((void**)&pwr, g_pwr);

    // side streams (created once; every call enqueues the identical DAG)
    static cudaStream_t s_dtx = nullptr, s_mw = nullptr, s_z = nullptr;
    static cudaEvent_t e_fork0 = nullptr, e_fork1 = nullptr;
    static cudaEvent_t e_dtx = nullptr, e_mw = nullptr, e_z = nullptr;
    if (s_dtx == nullptr) {
        int prLo = 0, prHi = 0;
        cudaDeviceGetStreamPriorityRange(&prLo, &prHi);   // prLo = lowest priority
        cudaStreamCreateWithFlags(&s_dtx, cudaStreamNonBlocking);
        cudaStreamCreateWithPriority(&s_mw, cudaStreamNonBlocking, prLo);
        cudaStreamCreateWithPriority(&s_z,  cudaStreamNonBlocking, prLo);
        cudaEventCreateWithFlags(&e_fork0, cudaEventDisableTiming);
        cudaEventCreateWithFlags(&e_fork1, cudaEventDisableTiming);
        cudaEventCreateWithFlags(&e_dtx,   cudaEventDisableTiming);
        cudaEventCreateWithFlags(&e_mw,    cudaEventDisableTiming);
        cudaEventCreateWithFlags(&e_z,     cudaEventDisableTiming);
    }

    dim3 blk(256);

    // fork: dtx is independent of all rounding work
    cudaEventRecord(e_fork0, 0);
    cudaStreamWaitEvent(s_dtx, e_fork0, 0);
    k_dtx<<<2*NB*LSEQ/8, blk, 0, s_dtx>>>(x, f_in_w, b_in_w, f_db, f_Al, b_db, b_Al);
    cudaEventRecord(e_dtx, s_dtx);

    long ntot = (long)NX + 2*NIW + NPW;
    k_round_all<<<(unsigned)((ntot + 255)/256), blk>>>(x, f_in_w, b_in_w, pw, xr, iwr, pwr);
    k_transT<<<dim3(DIN/32, DM/32, 2), blk>>>(f_ow, b_ow);

    // fork after rounding: mw (pwr+owT) and z-half of in_proj (xr+iwr) on low-prio streams
    cudaEventRecord(e_fork1, 0);
    cudaStreamWaitEvent(s_mw, e_fork1, 0);
    k_mw<<<dim3(DIN/TN, DM/TM, 2), blk, DSMEM, s_mw>>>();
    cudaEventRecord(e_mw, s_mw);

    cudaStreamWaitEvent(s_z, e_fork1, 0);
    k_in_proj<<<dim3(DIN/TN, (NB*LSEQ)/TM, 2), blk, DSMEM, s_z>>>(0);       // z: tiles 0..11
    cudaEventRecord(e_z, s_z);

    // critical path: xBC tiles 12..24 -> conv -> scan
    int nxbc = (DPROJ + TN - 1)/TN - DIN/TN;                                // 13 tiles
    k_in_proj<<<dim3(nxbc, (NB*LSEQ)/TM, 2), blk, DSMEM>>>(DIN/TN);

    long nconv = (long)2*NB*(LSEQ/4)*CONVD;
    k_conv<<<(unsigned)((nconv + 255)/256), blk>>>(f_cw, f_cb, b_cw, b_cb);

    cudaStreamWaitEvent(0, e_dtx, 0);   // join dtx before scan
    k_scanA<<<dim3(NCH, NH, NB*2), 64>>>();
    k_scanB<<<dim3(NH, NB, 2), 64>>>();
    k_scanC<<<dim3(NCH - 1, NH, NB*2), 64>>>();

    cudaStreamWaitEvent(0, e_z, 0);     // join z before gate (reads g_zx z-cols)
    k_gate_norm<<<2*NB*LSEQ, blk>>>(f_Dp, f_nw, b_Dp, b_nw);

    cudaStreamWaitEvent(0, e_mw, 0);    // join mw before final GEMM
    k_outf<<<dim3(DM/TN, (NB*LSEQ)/TM, 1), blk, DSMEM>>>(pb, out);
}

// round 16
// speedup vs baseline: 1.4745x; 1.1881x over previous
#include <cuda_runtime.h>
#include <cuda_fp16.h>
#include <math.h>
#include <stdint.h>

#define LSEQ  2048
#define NB    2
#define DM    768
#define DIN   1536
#define NH    24
#define HD    64
#define DS    16
#define CONVD 1568
#define DPROJ 3128

#define NCH 16
#define CT  (LSEQ/NCH)

#define TM 128
#define TN 128
#define GK 64                          // k-halfs per chunk
#define SROWH 72                       // halfs per smem row (64 + 4 pad)
#define STAGEB (2*128*SROWH*2)         // bytes per stage (A+B) = 36864
#define NSTAGE 3
#define DSMEM  (NSTAGE*STAGEB)         // 110592 B

// ---------------- scratch (device globals) ----------------------------------
__device__ float g_zx[2][NB][LSEQ][DPROJ];
__device__ float g_xc[2][NB][LSEQ][CONVD];
__device__ float g_dt[2][NB][LSEQ][NH];
__device__ float g_dA[2][NB][LSEQ][NH];
__device__ float g_y [2][NB][LSEQ][DIN];
__device__ float g_hend[2][NB][NH][NCH][HD][DS];
__device__ float g_hin [2][NB][NH][NCH][HD][DS];
__device__ float g_cpe [2][NB][NH][NCH];
// fp16 GEMM operands
__device__ __half g_xh  [NB*LSEQ*DM];
__device__ __half g_iwh [2][DPROJ*DM];
__device__ __half g_pwh [DM*2*DM];
__device__ __half g_owTh[2][DIN*DM];
__device__ __half g_Mh  [2][DM*DIN];
__device__ __half g_yh  [2][NB*LSEQ*DIN];

// ---------------- helpers ----------------------------------------------------
__device__ __forceinline__ uint32_t s2u(const void* p){
    uint32_t a;
    asm("{ .reg .u64 t; cvta.to.shared.u64 t, %1; cvt.u32.u64 %0, t; }" : "=r"(a) : "l"(p));
    return a;
}
__device__ __forceinline__ void cpa16(uint32_t dst, const void* src, bool p){
    int sz = p ? 16 : 0;
    asm volatile("cp.async.cg.shared.global [%0], [%1], 16, %2;"
                 :: "r"(dst), "l"(src), "r"(sz) : "memory");
}
#define CP_COMMIT() asm volatile("cp.async.commit_group;" ::: "memory")
#define CP_WAIT1()  asm volatile("cp.async.wait_group 1;" ::: "memory")
__device__ __forceinline__ void hmma(float* d, uint32_t a0, uint32_t a1, uint32_t a2,
                                     uint32_t a3, uint32_t b0, uint32_t b1){
    asm volatile("mma.sync.aligned.m16n8k16.row.col.f32.f16.f16.f32 "
                 "{%0,%1,%2,%3},{%4,%5,%6,%7},{%8,%9},{%0,%1,%2,%3};"
                 : "+f"(d[0]), "+f"(d[1]), "+f"(d[2]), "+f"(d[3])
                 : "r"(a0), "r"(a1), "r"(a2), "r"(a3), "r"(b0), "r"(b1));
}

// ---------------- fp16 mma.sync GEMM core ------------------------------------
// 256 threads, warp tile 32x64 (4 m-warps x 2 n-warps), CTA 128x128,
// cp.async 3-stage, GK=64, 144B-padded rows (conflict-free).
// acc[m,n] = sum_k A0[m,k]*B0[n,k] (+ A1*B1 if K1>0). A/B are __half.
// Output: float to Cbase (+bias) OR __half to Hbase.
__device__ __forceinline__ void gemm_hc(
    const __half* __restrict__ A0, long lda0, const __half* __restrict__ B0, int ldb0, int K0,
    const __half* __restrict__ A1, long lda1, const __half* __restrict__ B1, int ldb1, int K1,
    int nvalid, float* __restrict__ Cbase, __half* __restrict__ Hbase, long crs,
    const float* __restrict__ bias)
{
    extern __shared__ char dsm8[];
    const uint32_t smBase = s2u(dsm8);
    const int tid  = threadIdx.x;
    const int lane = tid & 31;
    const int wid  = tid >> 5;
    const int wm   = wid & 3;
    const int wn   = wid >> 2;
    const int g    = lane >> 2;
    const int tg   = lane & 3;

    float acc[2][8][4];
#pragma unroll
    for (int mt = 0; mt < 2; mt++)
#pragma unroll
        for (int nt = 0; nt < 8; nt++)
#pragma unroll
            for (int q = 0; q < 4; q++) acc[mt][nt][q] = 0.f;

    const int NC0 = K0 / GK;
    const int NC  = NC0 + K1 / GK;

    auto load = [&](int chunk, int s){
        const __half* Ab; long la; const __half* Bb; int lb; int kt;
        if (chunk < NC0) { Ab = A0; la = lda0; Bb = B0; lb = ldb0; kt = chunk*GK; }
        else             { Ab = A1; la = lda1; Bb = B1; lb = ldb1; kt = (chunk-NC0)*GK; }
        int row = tid >> 1;
        int u0  = (tid & 1) * 4;
        uint32_t stA = smBase + s*STAGEB + (uint32_t)row*144;
        uint32_t stB = stA + 128*144;
        const __half* arow = Ab + (long)row*la + kt;
        const __half* brow = Bb + (long)row*lb + kt;
        bool bp = row < nvalid;
#pragma unroll
        for (int u = u0; u < u0 + 4; u++) {
            cpa16(stA + u*16, arow + u*8, true);
            cpa16(stB + u*16, brow + u*8, bp);
        }
    };
    auto compute = [&](int s){
        const __half* As_ = (const __half*)(dsm8 + s*STAGEB);
        const __half* Bs_ = As_ + 128*SROWH;
#pragma unroll
        for (int ks = 0; ks < 4; ks++) {
            int ko = ks*16 + 2*tg;
            uint32_t af[2][4];
#pragma unroll
            for (int mt = 0; mt < 2; mt++) {
                const __half* ap = As_ + (wm*32 + mt*16 + g)*SROWH + ko;
                af[mt][0] = *(const uint32_t*)ap;
                af[mt][1] = *(const uint32_t*)(ap + 8*SROWH);
                af[mt][2] = *(const uint32_t*)(ap + 8);
                af[mt][3] = *(const uint32_t*)(ap + 8*SROWH + 8);
            }
            uint32_t bf[8][2];
#pragma unroll
            for (int nt = 0; nt < 8; nt++) {
                const __half* bp = Bs_ + (wn*64 + nt*8 + g)*SROWH + ko;
                bf[nt][0] = *(const uint32_t*)bp;
                bf[nt][1] = *(const uint32_t*)(bp + 8);
            }
#pragma unroll
            for (int mt = 0; mt < 2; mt++)
#pragma unroll
                for (int nt = 0; nt < 8; nt++)
                    hmma(acc[mt][nt], af[mt][0], af[mt][1], af[mt][2], af[mt][3],
                         bf[nt][0], bf[nt][1]);
        }
    };

    load(0, 0); CP_COMMIT();
    load(1, 1); CP_COMMIT();

    for (int i = 0; i < NC; i++) {
        CP_WAIT1();
        __syncthreads();
        if (i + 2 < NC) load(i + 2, (i + 2) % NSTAGE);
        CP_COMMIT();
        compute(i % NSTAGE);
    }

#pragma unroll
    for (int mt = 0; mt < 2; mt++) {
        int r0 = wm*32 + mt*16 + g;
#pragma unroll
        for (int nt = 0; nt < 8; nt++) {
            int col = wn*64 + nt*8 + 2*tg;
            float d0 = acc[mt][nt][0], d1 = acc[mt][nt][1];
            float d2 = acc[mt][nt][2], d3 = acc[mt][nt][3];
            if (bias) { d0 += bias[col]; d1 += bias[col+1]; d2 += bias[col]; d3 += bias[col+1]; }
            if (Hbase) {
                *(__half2*)(Hbase + (long)r0*crs + col)     = __floats2half2_rn(d0, d1);
                *(__half2*)(Hbase + (long)(r0+8)*crs + col) = __floats2half2_rn(d2, d3);
            } else if (col + 1 < nvalid) {
                *reinterpret_cast<float2*>(Cbase + (long)r0*crs + col)     = make_float2(d0, d1);
                *reinterpret_cast<float2*>(Cbase + (long)(r0+8)*crs + col) = make_float2(d2, d3);
            } else if (col < nvalid) {
                Cbase[(long)r0*crs + col]     = d0;
                Cbase[(long)(r0+8)*crs + col] = d2;
            }
        }
    }
}

// ---------------- GEMM wrappers ---------------------------------------------
__global__ __launch_bounds__(256) void k_in_proj(int ntile0)
{
    int dir = blockIdx.z, m0 = blockIdx.y*TM, n0 = (blockIdx.x + ntile0)*TN;
    int b = m0 >> 11, l0 = m0 & 2047;
    const __half* Abase; long ars;
    if (dir == 0) { Abase = g_xh + (size_t)m0*DM;                     ars =  DM; }
    else          { Abase = g_xh + ((size_t)b*LSEQ + (LSEQ-1-l0))*DM; ars = -(long)DM; }
    int nvalid = DPROJ - n0; if (nvalid > TN) nvalid = TN;
    gemm_hc(Abase, ars, &g_iwh[dir][0] + (size_t)n0*DM, DM, DM,
            nullptr, 0, nullptr, 0, 0,
            nvalid, &g_zx[dir][0][0][0] + (size_t)m0*DPROJ + n0, nullptr, DPROJ, nullptr);
}

// M[dir][m, n] = sum_j pw[m, j+dir*768] * ow[j, n]; stored fp16
__global__ __launch_bounds__(256) void k_mw()
{
    int dir = blockIdx.z, m0 = blockIdx.y*TM, n0 = blockIdx.x*TN;
    gemm_hc(g_pwh + (size_t)m0*(2*DM) + dir*DM, 2*DM,
            &g_owTh[dir][0] + (size_t)n0*DM, DM, DM,
            nullptr, 0, nullptr, 0, 0,
            TN, nullptr, &g_Mh[dir][0] + (size_t)m0*DIN + n0, DIN, nullptr);
}

// out[m, n] = sum_k y_f[m,k] Mf[n,k] + sum_k y_b[flip(m),k] Mb[n,k] + pb[n]
__global__ __launch_bounds__(256) void k_outf(const float* __restrict__ pb,
                                              float* __restrict__ out)
{
    int m0 = blockIdx.y*TM, n0 = blockIdx.x*TN;
    int b = m0 >> 11, l0 = m0 & 2047;
    gemm_hc(&g_yh[0][0] + (size_t)m0*DIN, DIN,
            &g_Mh[0][0] + (size_t)n0*DIN, DIN, DIN,
            &g_yh[1][0] + ((size_t)b*LSEQ + (LSEQ-1-l0))*DIN, -(long)DIN,
            &g_Mh[1][0] + (size_t)n0*DIN, DIN, DIN,
            TN, out + (size_t)m0*DM + n0, nullptr, DM, pb + n0);
}

// ---------------- fused fp16 conversion pass ---------------------------------
#define NX  (NB*LSEQ*DM)
#define NIW (DPROJ*DM)
#define NPW (DM*2*DM)
__global__ void k_cvt_all(const float* __restrict__ x,
                          const float* __restrict__ fiw, const float* __restrict__ biw,
                          const float* __restrict__ pw,
                          __half* __restrict__ xh, __half* __restrict__ iwh,
                          __half* __restrict__ pwh)
{
    long i = (long)blockIdx.x * 256 + threadIdx.x;
    if (i < NX)  { xh[i] = __float2half_rn(x[i]); return; }
    i -= NX;
    if (i < NIW) { iwh[i] = __float2half_rn(fiw[i]); return; }
    i -= NIW;
    if (i < NIW) { iwh[(long)NIW + i] = __float2half_rn(biw[i]); return; }
    i -= NIW;
    if (i < NPW) { pwh[i] = __float2half_rn(pw[i]); }
}

// ---------------- transpose + cvt out_w: (768,1536) -> (1536,768) fp16 -------
__global__ __launch_bounds__(256) void k_transT(const float* __restrict__ fow,
                                                const float* __restrict__ bow)
{
    __shared__ float tile[32][33];
    int dir = blockIdx.z;
    const float* src = dir ? bow : fow;
    int n0 = blockIdx.x * 32;
    int j0 = blockIdx.y * 32;
    int tx = threadIdx.x & 31, ty = threadIdx.x >> 5;
#pragma unroll
    for (int q = 0; q < 4; q++)
        tile[ty + q*8][tx] = src[(size_t)(j0 + ty + q*8)*DIN + n0 + tx];
    __syncthreads();
#pragma unroll
    for (int q = 0; q < 4; q++)
        g_owTh[dir][(size_t)(n0 + ty + q*8)*DM + j0 + tx] = __float2half_rn(tile[tx][ty + q*8]);
}

// ---------------- exact fp32 dt path ----------------------------------------
__global__ __launch_bounds__(256) void k_dtx(const float* __restrict__ x,
        const float* __restrict__ fw, const float* __restrict__ bw,
        const float* __restrict__ fdb, const float* __restrict__ fA,
        const float* __restrict__ bdb, const float* __restrict__ bA)
{
    __shared__ float sx[8][DM];
    int t = threadIdx.x, lane = t & 31, w = t >> 5;
    long gr0 = (long)blockIdx.x * 8;
    for (int i = t; i < 8*(DM/4); i += 256) {
        int r = i / (DM/4), c4 = i % (DM/4);
        long gr = gr0 + r;
        int l = gr & 2047; long rr = gr >> 11; int b = (int)(rr & 1), dir = (int)(rr >> 1);
        long srow = (long)b*LSEQ + (dir ? (LSEQ-1-l) : l);
        *(float4*)&sx[r][c4*4] = *(const float4*)(x + srow*DM + c4*4);
    }
    __syncthreads();
    long gr = gr0 + w;
    int l = gr & 2047; long rr = gr >> 11; int b = (int)(rr & 1), dir = (int)(rr >> 1);
    const float* W  = dir ? bw  : fw;
    const float* db = dir ? bdb : fdb;
    const float* Al = dir ? bA  : fA;
    for (int h = 0; h < NH; h++) {
        const float* wr = W + (size_t)(DIN + CONVD + h)*DM;
        float s = 0.f;
        for (int k = lane*4; k < DM; k += 128) {
            float4 a = *(const float4*)&sx[w][k];
            float4 ww = *(const float4*)(wr + k);
            s += a.x*ww.x + a.y*ww.y + a.z*ww.z + a.w*ww.w;
        }
#pragma unroll
        for (int o = 16; o; o >>= 1) s += __shfl_xor_sync(0xffffffffu, s, o);
        if (lane == 0) {
            float raw = s + db[h];
            float dt = raw > 20.f ? raw : log1pf(expf(raw));
            g_dt[dir][b][l][h] = dt;
            g_dA[dir][b][l][h] = expf(-expf(Al[h]) * dt);
        }
    }
}

// ---------------- depthwise causal conv(4) + SiLU (4 l per thread) ----------
__global__ void k_conv(const float* __restrict__ fcw, const float* __restrict__ fcb,
                       const float* __restrict__ bcw, const float* __restrict__ bcb)
{
    long idx = (long)blockIdx.x * 256 + threadIdx.x;
    if (idx >= (long)2*NB*(LSEQ/4)*CONVD) return;
    int c = (int)(idx % CONVD);
    long r = idx / CONVD;
    int lq = (int)(r % (LSEQ/4));  r /= (LSEQ/4);
    int b = (int)(r % NB);
    int dir = (int)(r / NB);
    const float* cw = dir ? bcw : fcw;
    float w0 = cw[c*4+0], w1 = cw[c*4+1], w2 = cw[c*4+2], w3 = cw[c*4+3];
    float cb = (dir ? bcb : fcb)[c];
    int l0 = lq * 4;
    const float* col = &g_zx[dir][b][0][DIN + c];
    float v[7];
#pragma unroll
    for (int k = 0; k < 7; k++) {
        int l = l0 - 3 + k;
        v[k] = (l >= 0) ? col[(size_t)l*DPROJ] : 0.f;
    }
#pragma unroll
    for (int i = 0; i < 4; i++) {
        float s = cb + v[i]*w0 + v[i+1]*w1 + v[i+2]*w2 + v[i+3]*w3;
        g_xc[dir][b][l0 + i][c] = s / (1.f + expf(-s));
    }
}

// ---------------- chunked scan: phase A (local scans) ------------------------
__global__ __launch_bounds__(64) void k_scanA()
{
    int c = blockIdx.x, h = blockIdx.y;
    int bz = blockIdx.z; int b = bz & 1, dir = bz >> 1;
    int t = threadIdx.x;
    __shared__ float sx[32][HD];
    __shared__ __align__(16) float sB[32][DS];
    __shared__ float sdt[32], sdA[32];
    __shared__ __align__(16) float sC[32][DS];
    float hs[DS];
#pragma unroll
    for (int j = 0; j < DS; j++) hs[j] = 0.f;
    float cp = 1.f;
    int base = c * CT;

    for (int l0 = 0; l0 < CT; l0 += 32) {
#pragma unroll 4
        for (int j = 0; j < 32; j++)
            sx[j][t] = g_xc[dir][b][base + l0 + j][h*HD + t];
        for (int i = t; i < 32*DS; i += 64) {
            int s = i >> 4, j = i & 15;
            sB[s][j] = g_xc[dir][b][base + l0 + s][DIN + j];
            sC[s][j] = g_xc[dir][b][base + l0 + s][DIN + DS + j];
        }
        if (t < 32) {
            sdt[t] = g_dt[dir][b][base + l0 + t][h];
            sdA[t] = g_dA[dir][b][base + l0 + t][h];
        }
        __syncthreads();
#pragma unroll 2
        for (int s = 0; s < 32; s++) {
            float dAv = sdA[s];
            cp *= dAv;
            float xv  = sdt[s] * sx[s][t];
            float4 B0 = *(const float4*)&sB[s][0];
            float4 B1 = *(const float4*)&sB[s][4];
            float4 B2 = *(const float4*)&sB[s][8];
            float4 B3 = *(const float4*)&sB[s][12];
            float4 C0 = *(const float4*)&sC[s][0];
            float4 C1 = *(const float4*)&sC[s][4];
            float4 C2 = *(const float4*)&sC[s][8];
            float4 C3 = *(const float4*)&sC[s][12];
            float y = 0.f;
            hs[0]  = hs[0]*dAv  + xv*B0.x;  y += hs[0]*C0.x;
            hs[1]  = hs[1]*dAv  + xv*B0.y;  y += hs[1]*C0.y;
            hs[2]  = hs[2]*dAv  + xv*B0.z;  y += hs[2]*C0.z;
            hs[3]  = hs[3]*dAv  + xv*B0.w;  y += hs[3]*C0.w;
            hs[4]  = hs[4]*dAv  + xv*B1.x;  y += hs[4]*C1.x;
            hs[5]  = hs[5]*dAv  + xv*B1.y;  y += hs[5]*C1.y;
            hs[6]  = hs[6]*dAv  + xv*B1.z;  y += hs[6]*C1.z;
            hs[7]  = hs[7]*dAv  + xv*B1.w;  y += hs[7]*C1.w;
            hs[8]  = hs[8]*dAv  + xv*B2.x;  y += hs[8]*C2.x;
            hs[9]  = hs[9]*dAv  + xv*B2.y;  y += hs[9]*C2.y;
            hs[10] = hs[10]*dAv + xv*B2.z;  y += hs[10]*C2.z;
            hs[11] = hs[11]*dAv + xv*B2.w;  y += hs[11]*C2.w;
            hs[12] = hs[12]*dAv + xv*B3.x;  y += hs[12]*C3.x;
            hs[13] = hs[13]*dAv + xv*B3.y;  y += hs[13]*C3.y;
            hs[14] = hs[14]*dAv + xv*B3.z;  y += hs[14]*C3.z;
            hs[15] = hs[15]*dAv + xv*B3.w;  y += hs[15]*C3.w;
            g_y[dir][b][base + l0 + s][h*HD + t] = y;
        }
        __syncthreads();
    }
    float4* he = (float4*)&g_hend[dir][b][h][c][t][0];
    he[0] = make_float4(hs[0], hs[1], hs[2], hs[3]);
    he[1] = make_float4(hs[4], hs[5], hs[6], hs[7]);
    he[2] = make_float4(hs[8], hs[9], hs[10], hs[11]);
    he[3] = make_float4(hs[12], hs[13], hs[14], hs[15]);
    if (t == 0) g_cpe[dir][b][h][c] = cp;
}

// ---------------- chunked scan: phase B (chunk prefix) -----------------------
__global__ __launch_bounds__(64) void k_scanB()
{
    int h = blockIdx.x, b = blockIdx.y, dir = blockIdx.z;
    int t = threadIdx.x;
    float hin[DS];
#pragma unroll
    for (int j = 0; j < DS; j++) hin[j] = 0.f;
    for (int c = 0; c < NCH; c++) {
        float4* hp = (float4*)&g_hin[dir][b][h][c][t][0];
        hp[0] = make_float4(hin[0], hin[1], hin[2], hin[3]);
        hp[1] = make_float4(hin[4], hin[5], hin[6], hin[7]);
        hp[2] = make_float4(hin[8], hin[9], hin[10], hin[11]);
        hp[3] = make_float4(hin[12], hin[13], hin[14], hin[15]);
        float cpe = g_cpe[dir][b][h][c];
        const float4* he = (const float4*)&g_hend[dir][b][h][c][t][0];
        float4 e0 = he[0], e1 = he[1], e2 = he[2], e3 = he[3];
        hin[0]  = hin[0]*cpe  + e0.x;  hin[1]  = hin[1]*cpe  + e0.y;
        hin[2]  = hin[2]*cpe  + e0.z;  hin[3]  = hin[3]*cpe  + e0.w;
        hin[4]  = hin[4]*cpe  + e1.x;  hin[5]  = hin[5]*cpe  + e1.y;
        hin[6]  = hin[6]*cpe  + e1.z;  hin[7]  = hin[7]*cpe  + e1.w;
        hin[8]  = hin[8]*cpe  + e2.x;  hin[9]  = hin[9]*cpe  + e2.y;
        hin[10] = hin[10]*cpe + e2.z;  hin[11] = hin[11]*cpe + e2.w;
        hin[12] = hin[12]*cpe + e3.x;  hin[13] = hin[13]*cpe + e3.y;
        hin[14] = hin[14]*cpe + e3.z;  hin[15] = hin[15]*cpe + e3.w;
    }
}

// ---------------- chunked scan: phase C (carry-in correction) ----------------
__global__ __launch_bounds__(64) void k_scanC()
{
    int c = blockIdx.x + 1;
    int h = blockIdx.y;
    int bz = blockIdx.z; int b = bz & 1, dir = bz >> 1;
    int t = threadIdx.x;
    __shared__ __align__(16) float sC[32][DS];
    __shared__ float sdA[32];
    float hin[DS];
    {
        const float4* hp = (const float4*)&g_hin[dir][b][h][c][t][0];
        float4 a0 = hp[0], a1 = hp[1], a2 = hp[2], a3 = hp[3];
        hin[0]=a0.x; hin[1]=a0.y; hin[2]=a0.z; hin[3]=a0.w;
        hin[4]=a1.x; hin[5]=a1.y; hin[6]=a1.z; hin[7]=a1.w;
        hin[8]=a2.x; hin[9]=a2.y; hin[10]=a2.z; hin[11]=a2.w;
        hin[12]=a3.x; hin[13]=a3.y; hin[14]=a3.z; hin[15]=a3.w;
    }
    float cp = 1.f;
    int base = c * CT;
    for (int l0 = 0; l0 < CT; l0 += 32) {
        for (int i = t; i < 32*DS; i += 64) {
            int s = i >> 4, j = i & 15;
            sC[s][j] = g_xc[dir][b][base + l0 + s][DIN + DS + j];
        }
        if (t < 32) sdA[t] = g_dA[dir][b][base + l0 + t][h];
        __syncthreads();
#pragma unroll 4
        for (int s = 0; s < 32; s++) {
            cp *= sdA[s];
            float4 C0 = *(const float4*)&sC[s][0];
            float4 C1 = *(const float4*)&sC[s][4];
            float4 C2 = *(const float4*)&sC[s][8];
            float4 C3 = *(const float4*)&sC[s][12];
            float d = hin[0]*C0.x + hin[1]*C0.y + hin[2]*C0.z + hin[3]*C0.w
                    + hin[4]*C1.x + hin[5]*C1.y + hin[6]*C1.z + hin[7]*C1.w
                    + hin[8]*C2.x + hin[9]*C2.y + hin[10]*C2.z + hin[11]*C2.w
                    + hin[12]*C3.x + hin[13]*C3.y + hin[14]*C3.z + hin[15]*C3.w;
            g_y[dir][b][base + l0 + s][h*HD + t] += cp * d;
        }
        __syncthreads();
    }
}

// ---- y += Dp*xh; gate silu(z); RMSNorm; store fp16 --------------------------
__global__ void k_gate_norm(const float* __restrict__ fDp, const float* __restrict__ fnw,
                            const float* __restrict__ bDp, const float* __restrict__ bnw)
{
    int row = blockIdx.x;
    int l = row % LSEQ;
    int r = row / LSEQ;
    int b = r % NB;
    int dir = r / NB;
    const float* Dp = dir ? bDp : fDp;
    const float* nw = dir ? bnw : fnw;
    float vals[6];
    float sq = 0.f;
#pragma unroll
    for (int ii = 0; ii < 6; ii++) {
        int i = threadIdx.x + ii*256;
        int hh = i >> 6;
        float xh = g_xc[dir][b][l][i];
        float yv = g_y[dir][b][l][i] + Dp[hh]*xh;
        float z  = g_zx[dir][b][l][i];
        yv *= z / (1.f + expf(-z));
        vals[ii] = yv;
        sq += yv*yv;
    }
#pragma unroll
    for (int o = 16; o; o >>= 1) sq += __shfl_xor_sync(0xffffffffu, sq, o);
    __shared__ float ssum[8];
    __shared__ float sscale;
    int w = threadIdx.x >> 5;
    if ((threadIdx.x & 31) == 0) ssum[w] = sq;
    __syncthreads();
    if (threadIdx.x == 0) {
        float tot = 0.f;
        for (int i = 0; i < 8; i++) tot += ssum[i];
        sscale = rsqrtf(tot/(float)DIN + 1e-5f);
    }
    __syncthreads();
    float scale = sscale;
    __half* yrow = &g_yh[dir][((size_t)b*LSEQ + l)*DIN];
#pragma unroll
    for (int ii = 0; ii < 6; ii++) {
        int i = threadIdx.x + ii*256;
        yrow[i] = __float2half_rn(vals[ii]*scale*nw[i]);
    }
}

// ---------------- launch -----------------------------------------------------
extern "C" void kernel_launch(void* const* d_in, const int* in_sizes, int n_in,
                              void* d_out, int out_size)
{
    const float* x      = (const float*)d_in[0];
    const float* pw     = (const float*)d_in[1];
    const float* pb     = (const float*)d_in[2];
    const float* f_in_w = (const float*)d_in[3];
    const float* f_cw   = (const float*)d_in[4];
    const float* f_cb   = (const float*)d_in[5];
    const float* f_db   = (const float*)d_in[6];
    const float* f_Al   = (const float*)d_in[7];
    const float* f_Dp   = (const float*)d_in[8];
    const float* f_nw   = (const float*)d_in[9];
    const float* f_ow   = (const float*)d_in[10];
    const float* b_in_w = (const float*)d_in[11];
    const float* b_cw   = (const float*)d_in[12];
    const float* b_cb   = (const float*)d_in[13];
    const float* b_db   = (const float*)d_in[14];
    const float* b_Al   = (const float*)d_in[15];
    const float* b_Dp   = (const float*)d_in[16];
    const float* b_nw   = (const float*)d_in[17];
    const float* b_ow   = (const float*)d_in[18];
    float* out = (float*)d_out;

    cudaFuncSetAttribute(k_in_proj, cudaFuncAttributeMaxDynamicSharedMemorySize, DSMEM);
    cudaFuncSetAttribute(k_mw,      cudaFuncAttributeMaxDynamicSharedMemorySize, DSMEM);
    cudaFuncSetAttribute(k_outf,    cudaFuncAttributeMaxDynamicSharedMemorySize, DSMEM);

    __half* xh  = nullptr; cudaGetSymbolAddress((void**)&xh,  g_xh);
    __half* iwh = nullptr; cudaGetSymbolAddress((void**)&iwh, g_iwh);
    __half* pwh = nullptr; cudaGetSymbolAddress((void**)&pwh, g_pwh);

    static cudaStream_t s_dtx = nullptr, s_mw = nullptr, s_z = nullptr;
    static cudaEvent_t e_fork0 = nullptr, e_fork1 = nullptr;
    static cudaEvent_t e_dtx = nullptr, e_mw = nullptr, e_z = nullptr;
    if (s_dtx == nullptr) {
        int prLo = 0, prHi = 0;
        cudaDeviceGetStreamPriorityRange(&prLo, &prHi);
        cudaStreamCreateWithFlags(&s_dtx, cudaStreamNonBlocking);
        cudaStreamCreateWithPriority(&s_mw, cudaStreamNonBlocking, prLo);
        cudaStreamCreateWithPriority(&s_z,  cudaStreamNonBlocking, prLo);
        cudaEventCreateWithFlags(&e_fork0, cudaEventDisableTiming);
        cudaEventCreateWithFlags(&e_fork1, cudaEventDisableTiming);
        cudaEventCreateWithFlags(&e_dtx,   cudaEventDisableTiming);
        cudaEventCreateWithFlags(&e_mw,    cudaEventDisableTiming);
        cudaEventCreateWithFlags(&e_z,     cudaEventDisableTiming);
    }

    dim3 blk(256);

    cudaEventRecord(e_fork0, 0);
    cudaStreamWaitEvent(s_dtx, e_fork0, 0);
    k_dtx<<<2*NB*LSEQ/8, blk, 0, s_dtx>>>(x, f_in_w, b_in_w, f_db, f_Al, b_db, b_Al);
    cudaEventRecord(e_dtx, s_dtx);

    long ntot = (long)NX + 2*NIW + NPW;
    k_cvt_all<<<(unsigned)((ntot + 255)/256), blk>>>(x, f_in_w, b_in_w, pw, xh, iwh, pwh);
    k_transT<<<dim3(DIN/32, DM/32, 2), blk>>>(f_ow, b_ow);

    cudaEventRecord(e_fork1, 0);
    cudaStreamWaitEvent(s_mw, e_fork1, 0);
    k_mw<<<dim3(DIN/TN, DM/TM, 2), blk, DSMEM, s_mw>>>();
    cudaEventRecord(e_mw, s_mw);

    cudaStreamWaitEvent(s_z, e_fork1, 0);
    k_in_proj<<<dim3(DIN/TN, (NB*LSEQ)/TM, 2), blk, DSMEM, s_z>>>(0);      // z tiles
    cudaEventRecord(e_z, s_z);

    int nxbc = (DPROJ + TN - 1)/TN - DIN/TN;                               // xBC tiles
    k_in_proj<<<dim3(nxbc, (NB*LSEQ)/TM, 2), blk, DSMEM>>>(DIN/TN);

    long nconv = (long)2*NB*(LSEQ/4)*CONVD;
    k_conv<<<(unsigned)((nconv + 255)/256), blk>>>(f_cw, f_cb, b_cw, b_cb);

    cudaStreamWaitEvent(0, e_dtx, 0);
    k_scanA<<<dim3(NCH, NH, NB*2), 64>>>();
    k_scanB<<<dim3(NH, NB, 2), 64>>>();
    k_scanC<<<dim3(NCH - 1, NH, NB*2), 64>>>();

    cudaStreamWaitEvent(0, e_z, 0);
    k_gate_norm<<<2*NB*LSEQ, blk>>>(f_Dp, f_nw, b_Dp, b_nw);

    cudaStreamWaitEvent(0, e_mw, 0);
    k_outf<<<dim3(DM/TN, (NB*LSEQ)/TM, 1), blk, DSMEM>>>(pb, out);
}